// round 1
// baseline (speedup 1.0000x reference)
#include <cuda_runtime.h>

// Problem constants
#define B_  2
#define H_  4
#define SL  4096
#define D_  256
#define HD  64

// Scratch (allocation-free rule: __device__ globals)
__device__ float g_Q[B_ * H_ * SL * HD];   // [B,H,S,64], pre-scaled by 1/8
__device__ float g_K[B_ * H_ * SL * HD];   // [B,H,S,64]
__device__ float g_V[B_ * H_ * SL * HD];   // [B,H,S,64]
__device__ float g_AT[B_ * SL * D_];       // attention output [B,S,256]

// ---------------------------------------------------------------------------
// GEMM: C = (A @ W^T + bias) * outScale
//   A [M,256] row-major, W [256,256] row-major (torch Linear weight layout)
//   MODE 0: C row-major [M,256]
//   MODE 1: C as [B,H,S,64]  (n-tile == head because BN==64==HD)
// 64x64 tile, 256 threads (16x16), 4x4 per-thread fragment, BK=32.
// ---------------------------------------------------------------------------
template <int MODE>
__global__ __launch_bounds__(256) void gemm_kernel(
    const float* __restrict__ A, const float* __restrict__ W,
    const float* __restrict__ bias, float* __restrict__ C, float outScale)
{
    __shared__ float As[64][33];   // pad 33: frag read bank = (r+kk)%32, conflict-free
    __shared__ float Ws[64][33];

    const int t  = threadIdx.x;
    const int tx = t & 15, ty = t >> 4;
    const int m0 = blockIdx.x * 64, n0 = blockIdx.y * 64;

    float acc[4][4] = {};

    for (int k0 = 0; k0 < 256; k0 += 32) {
        __syncthreads();
        #pragma unroll
        for (int i = 0; i < 2; i++) {
            int f  = t + i * 256;
            int r  = f >> 3;
            int c4 = (f & 7) << 2;
            float4 av = *(const float4*)(A + (size_t)(m0 + r) * 256 + k0 + c4);
            As[r][c4 + 0] = av.x; As[r][c4 + 1] = av.y;
            As[r][c4 + 2] = av.z; As[r][c4 + 3] = av.w;
            float4 wv = *(const float4*)(W + (size_t)(n0 + r) * 256 + k0 + c4);
            Ws[r][c4 + 0] = wv.x; Ws[r][c4 + 1] = wv.y;
            Ws[r][c4 + 2] = wv.z; Ws[r][c4 + 3] = wv.w;
        }
        __syncthreads();

        #pragma unroll 8
        for (int kk = 0; kk < 32; kk++) {
            float a[4], b[4];
            #pragma unroll
            for (int i = 0; i < 4; i++) a[i] = As[4 * ty + i][kk];
            #pragma unroll
            for (int j = 0; j < 4; j++) b[j] = Ws[4 * tx + j][kk];
            #pragma unroll
            for (int i = 0; i < 4; i++)
                #pragma unroll
                for (int j = 0; j < 4; j++)
                    acc[i][j] += a[i] * b[j];
        }
    }

    #pragma unroll
    for (int i = 0; i < 4; i++) {
        int m = m0 + 4 * ty + i;
        float4 ov;
        ov.x = (acc[i][0] + bias[n0 + 4 * tx + 0]) * outScale;
        ov.y = (acc[i][1] + bias[n0 + 4 * tx + 1]) * outScale;
        ov.z = (acc[i][2] + bias[n0 + 4 * tx + 2]) * outScale;
        ov.w = (acc[i][3] + bias[n0 + 4 * tx + 3]) * outScale;
        if (MODE == 0) {
            *(float4*)(C + (size_t)m * 256 + n0 + 4 * tx) = ov;
        } else {
            int bb   = m >> 12;          // m / SL
            int srow = m & (SL - 1);
            *(float4*)(C + ((size_t)(bb * H_ + blockIdx.y) * SL + srow) * HD + 4 * tx) = ov;
        }
    }
}

// ---------------------------------------------------------------------------
// Flash attention, fp32. One block = 64 query rows of one (b,h).
// 256 threads (16x16), 4x4 fragments for both QK^T and PV.
// Smem layouts chosen so every fragment load is a conflict-free LDS.128:
//   Qt[d][r]  (stride 68)   a-frag  = float4 @ Qt[kk*68 + 4*ty]   (broadcast)
//   Kt[d][c]  (stride 68)   b-frag  = float4 @ Kt[kk*68 + 4*tx]   (contiguous)
//   Pt[c][r]  (stride 68)   p-frag  = float4 @ Pt[cc*68 + 4*ty]
//   Vs[c][d]  (stride 64)   v-frag  = float4 @ Vs[cc*64 + 4*tx]
// ---------------------------------------------------------------------------
__global__ __launch_bounds__(256) void flash_attn_kernel(
    const float* __restrict__ Q, const float* __restrict__ K,
    const float* __restrict__ V, const int* __restrict__ mask,
    float* __restrict__ O)
{
    extern __shared__ float sm[];
    float* Qt = sm;                  // 64*68
    float* Kt = sm + 64 * 68;        // 64*68
    float* Pt = sm + 2 * 64 * 68;    // 64*68
    float* Vs = sm + 3 * 64 * 68;    // 64*64

    const int t  = threadIdx.x;
    const int tx = t & 15, ty = t >> 4;
    const int q0 = blockIdx.x * 64;
    const int h  = blockIdx.y;
    const int b  = blockIdx.z;

    const float* Qb = Q + ((size_t)(b * H_ + h) * SL + q0) * HD;
    const float* Kb = K + (size_t)(b * H_ + h) * SL * HD;
    const float* Vb = V + (size_t)(b * H_ + h) * SL * HD;

    // Load Q tile transposed (once per block)
    #pragma unroll
    for (int i = 0; i < 4; i++) {
        int f  = t + i * 256;
        int r  = f >> 4;
        int d4 = (f & 15) << 2;
        float4 qv = *(const float4*)(Qb + r * HD + d4);
        Qt[(d4 + 0) * 68 + r] = qv.x;
        Qt[(d4 + 1) * 68 + r] = qv.y;
        Qt[(d4 + 2) * 68 + r] = qv.z;
        Qt[(d4 + 3) * 68 + r] = qv.w;
    }

    float oacc[4][4] = {};
    float rm[4], rl[4];
    #pragma unroll
    for (int i = 0; i < 4; i++) { rm[i] = -3.0e38f; rl[i] = 0.0f; }

    for (int kb = 0; kb < SL; kb += 64) {
        __syncthreads();   // protects Kt/Vs from previous iteration's readers
        #pragma unroll
        for (int i = 0; i < 4; i++) {
            int f  = t + i * 256;
            int r  = f >> 4;
            int d4 = (f & 15) << 2;
            float4 kv = *(const float4*)(Kb + (size_t)(kb + r) * HD + d4);
            Kt[(d4 + 0) * 68 + r] = kv.x;
            Kt[(d4 + 1) * 68 + r] = kv.y;
            Kt[(d4 + 2) * 68 + r] = kv.z;
            Kt[(d4 + 3) * 68 + r] = kv.w;
            float4 vv = *(const float4*)(Vb + (size_t)(kb + r) * HD + d4);
            *(float4*)(Vs + r * HD + d4) = vv;
        }
        __syncthreads();

        // S = Q K^T  (Q pre-scaled by 1/8)
        float s[4][4] = {};
        #pragma unroll 8
        for (int kk = 0; kk < 64; kk++) {
            float a[4], bb[4];
            *(float4*)a  = *(const float4*)(Qt + kk * 68 + 4 * ty);
            *(float4*)bb = *(const float4*)(Kt + kk * 68 + 4 * tx);
            #pragma unroll
            for (int i = 0; i < 4; i++)
                #pragma unroll
                for (int j = 0; j < 4; j++)
                    s[i][j] += a[i] * bb[j];
        }

        // Mask (broadcast over b,h), matching reference's -1e9 fill
        #pragma unroll
        for (int i = 0; i < 4; i++) {
            int4 mv = *(const int4*)(mask + (size_t)(q0 + 4 * ty + i) * SL + kb + 4 * tx);
            if (mv.x == 0) s[i][0] = -1e9f;
            if (mv.y == 0) s[i][1] = -1e9f;
            if (mv.z == 0) s[i][2] = -1e9f;
            if (mv.w == 0) s[i][3] = -1e9f;
        }

        // Online softmax; row groups are the 16 lanes sharing ty (xor 1,2,4,8
        // stays inside each 16-lane half of the warp)
        #pragma unroll
        for (int i = 0; i < 4; i++) {
            float tm = fmaxf(fmaxf(s[i][0], s[i][1]), fmaxf(s[i][2], s[i][3]));
            tm = fmaxf(tm, __shfl_xor_sync(0xffffffffu, tm, 1));
            tm = fmaxf(tm, __shfl_xor_sync(0xffffffffu, tm, 2));
            tm = fmaxf(tm, __shfl_xor_sync(0xffffffffu, tm, 4));
            tm = fmaxf(tm, __shfl_xor_sync(0xffffffffu, tm, 8));
            float nm   = fmaxf(rm[i], tm);
            float corr = __expf(rm[i] - nm);
            float pl = 0.0f;
            #pragma unroll
            for (int j = 0; j < 4; j++) {
                float p = __expf(s[i][j] - nm);
                s[i][j] = p;
                pl += p;
            }
            pl += __shfl_xor_sync(0xffffffffu, pl, 1);
            pl += __shfl_xor_sync(0xffffffffu, pl, 2);
            pl += __shfl_xor_sync(0xffffffffu, pl, 4);
            pl += __shfl_xor_sync(0xffffffffu, pl, 8);
            rl[i] = rl[i] * corr + pl;
            rm[i] = nm;
            #pragma unroll
            for (int j = 0; j < 4; j++) oacc[i][j] *= corr;
            #pragma unroll
            for (int j = 0; j < 4; j++) Pt[(4 * tx + j) * 68 + 4 * ty + i] = s[i][j];
        }
        __syncthreads();

        // O += P V
        #pragma unroll 8
        for (int cc = 0; cc < 64; cc++) {
            float p[4], v[4];
            *(float4*)p = *(const float4*)(Pt + cc * 68 + 4 * ty);
            *(float4*)v = *(const float4*)(Vs + cc * HD + 4 * tx);
            #pragma unroll
            for (int i = 0; i < 4; i++)
                #pragma unroll
                for (int j = 0; j < 4; j++)
                    oacc[i][j] += p[i] * v[j];
        }
    }

    // Normalize and store as [B,S,256] with head-concat layout
    float* Ob = O + ((size_t)b * SL + q0) * D_ + h * HD;
    #pragma unroll
    for (int i = 0; i < 4; i++) {
        float inv = 1.0f / rl[i];
        float4 ov;
        ov.x = oacc[i][0] * inv;
        ov.y = oacc[i][1] * inv;
        ov.z = oacc[i][2] * inv;
        ov.w = oacc[i][3] * inv;
        *(float4*)(Ob + (size_t)(4 * ty + i) * D_ + 4 * tx) = ov;
    }
}

// ---------------------------------------------------------------------------
extern "C" void kernel_launch(void* const* d_in, const int* in_sizes, int n_in,
                              void* d_out, int out_size)
{
    const float* x_logic  = (const float*)d_in[0];
    const float* x_memory = (const float*)d_in[1];
    const int*   mask     = (const int*)  d_in[2];
    const float* Wq = (const float*)d_in[3];
    const float* bq = (const float*)d_in[4];
    const float* Wk = (const float*)d_in[5];
    const float* bk = (const float*)d_in[6];
    const float* Wv = (const float*)d_in[7];
    const float* bv = (const float*)d_in[8];
    const float* Wo = (const float*)d_in[9];
    const float* bo = (const float*)d_in[10];
    float* out = (float*)d_out;

    float *gQ, *gK, *gV, *gA;
    cudaGetSymbolAddress((void**)&gQ, g_Q);
    cudaGetSymbolAddress((void**)&gK, g_K);
    cudaGetSymbolAddress((void**)&gV, g_V);
    cudaGetSymbolAddress((void**)&gA, g_AT);

    const int M = B_ * SL;            // 8192
    dim3 gg(M / 64, D_ / 64);         // 128 x 4

    // Q gets the 1/sqrt(head_dim)=0.125 scale folded into its projection.
    gemm_kernel<1><<<gg, 256>>>(x_logic,  Wq, bq, gQ, 0.125f);
    gemm_kernel<1><<<gg, 256>>>(x_logic,  Wk, bk, gK, 1.0f);
    gemm_kernel<1><<<gg, 256>>>(x_memory, Wv, bv, gV, 1.0f);

    const int smem_bytes = (3 * 64 * 68 + 64 * 64) * (int)sizeof(float);  // 68608
    cudaFuncSetAttribute(flash_attn_kernel,
                         cudaFuncAttributeMaxDynamicSharedMemorySize, smem_bytes);
    dim3 ga(SL / 64, H_, B_);         // 64 x 4 x 2 = 512 blocks
    flash_attn_kernel<<<ga, 256, smem_bytes>>>(gQ, gK, gV, mask, gA);

    gemm_kernel<0><<<gg, 256>>>(gA, Wo, bo, out, 1.0f);
}

// round 3
// speedup vs baseline: 2.6349x; 2.6349x over previous
#include <cuda_runtime.h>
#include <cstdint>

// Problem constants
#define B_  2
#define H_  4
#define SL  4096
#define D_  256
#define HD  64

// Scratch (allocation-free rule: __device__ globals)
__device__ float    g_Q[B_ * H_ * SL * HD];   // [B,H,S,64], pre-scaled by 1/8
__device__ float    g_K[B_ * H_ * SL * HD];
__device__ float    g_V[B_ * H_ * SL * HD];
__device__ float    g_AT[B_ * SL * D_];       // attention output [B,S,256]
__device__ unsigned g_M[SL * SL / 32];        // packed mask bits

// ---------------------------------------------------------------------------
// helpers
// ---------------------------------------------------------------------------
__device__ __forceinline__ uint32_t f2tf32(float x) {
    uint32_t u;
    asm("cvt.rna.tf32.f32 %0, %1;" : "=r"(u) : "f"(x));
    return u;
}

__device__ __forceinline__ void mma_tf32(float d[4], const uint32_t a[4],
                                         uint32_t b0, uint32_t b1) {
    asm volatile(
        "mma.sync.aligned.m16n8k8.row.col.f32.tf32.tf32.f32 "
        "{%0,%1,%2,%3}, {%4,%5,%6,%7}, {%8,%9}, {%0,%1,%2,%3};"
        : "+f"(d[0]), "+f"(d[1]), "+f"(d[2]), "+f"(d[3])
        : "r"(a[0]), "r"(a[1]), "r"(a[2]), "r"(a[3]), "r"(b0), "r"(b1));
}

// ---------------------------------------------------------------------------
// Pack int32 mask [S,S] into bitmask (1 bit/element). word idx covers 32
// consecutive row-major elements; 128 words per row.
// ---------------------------------------------------------------------------
__global__ __launch_bounds__(256) void mask_pack_kernel(
    const int* __restrict__ mask, unsigned* __restrict__ out)
{
    int idx = blockIdx.x * 256 + threadIdx.x;
    const int* p = mask + (size_t)idx * 32;
    unsigned w = 0;
    #pragma unroll
    for (int i = 0; i < 32; i += 4) {
        int4 v = *(const int4*)(p + i);
        if (v.x) w |= 1u << i;
        if (v.y) w |= 1u << (i + 1);
        if (v.z) w |= 1u << (i + 2);
        if (v.w) w |= 1u << (i + 3);
    }
    out[idx] = w;
}

// ---------------------------------------------------------------------------
// GEMM: C = (A @ W^T + bias) * outScale   (fp32 register-tiled)
// ---------------------------------------------------------------------------
template <int MODE>
__global__ __launch_bounds__(256) void gemm_kernel(
    const float* __restrict__ A, const float* __restrict__ W,
    const float* __restrict__ bias, float* __restrict__ C, float outScale)
{
    __shared__ float As[64][33];
    __shared__ float Ws[64][33];

    const int t  = threadIdx.x;
    const int tx = t & 15, ty = t >> 4;
    const int m0 = blockIdx.x * 64, n0 = blockIdx.y * 64;

    float acc[4][4] = {};

    for (int k0 = 0; k0 < 256; k0 += 32) {
        __syncthreads();
        #pragma unroll
        for (int i = 0; i < 2; i++) {
            int f  = t + i * 256;
            int r  = f >> 3;
            int c4 = (f & 7) << 2;
            float4 av = *(const float4*)(A + (size_t)(m0 + r) * 256 + k0 + c4);
            As[r][c4 + 0] = av.x; As[r][c4 + 1] = av.y;
            As[r][c4 + 2] = av.z; As[r][c4 + 3] = av.w;
            float4 wv = *(const float4*)(W + (size_t)(n0 + r) * 256 + k0 + c4);
            Ws[r][c4 + 0] = wv.x; Ws[r][c4 + 1] = wv.y;
            Ws[r][c4 + 2] = wv.z; Ws[r][c4 + 3] = wv.w;
        }
        __syncthreads();

        #pragma unroll 8
        for (int kk = 0; kk < 32; kk++) {
            float a[4], b[4];
            #pragma unroll
            for (int i = 0; i < 4; i++) a[i] = As[4 * ty + i][kk];
            #pragma unroll
            for (int j = 0; j < 4; j++) b[j] = Ws[4 * tx + j][kk];
            #pragma unroll
            for (int i = 0; i < 4; i++)
                #pragma unroll
                for (int j = 0; j < 4; j++)
                    acc[i][j] += a[i] * b[j];
        }
    }

    #pragma unroll
    for (int i = 0; i < 4; i++) {
        int m = m0 + 4 * ty + i;
        float4 ov;
        ov.x = (acc[i][0] + bias[n0 + 4 * tx + 0]) * outScale;
        ov.y = (acc[i][1] + bias[n0 + 4 * tx + 1]) * outScale;
        ov.z = (acc[i][2] + bias[n0 + 4 * tx + 2]) * outScale;
        ov.w = (acc[i][3] + bias[n0 + 4 * tx + 3]) * outScale;
        if (MODE == 0) {
            *(float4*)(C + (size_t)m * 256 + n0 + 4 * tx) = ov;
        } else {
            int bb   = m >> 12;
            int srow = m & (SL - 1);
            *(float4*)(C + ((size_t)(bb * H_ + blockIdx.y) * SL + srow) * HD + 4 * tx) = ov;
        }
    }
}

// ---------------------------------------------------------------------------
// Flash attention on tensor cores (tf32 mma.sync m16n8k8).
// Block: 8 warps, 128 q-rows (warp w owns rows q0 + w*16). Key tile = 64.
// Smem (dynamic):
//   Ks [64 key][68]   tf32 bits   (frag bank = g*4+tig+c -> conflict-free)
//   Vs [64 key][72]   tf32 bits   (frag bank = tig*8+g   -> conflict-free)
//   Ps [warp][16][68] tf32 bits   (P staging; also Q staging at start)
// ---------------------------------------------------------------------------
#define KS_STRIDE 68
#define VS_STRIDE 72
#define PS_STRIDE 68
#define KS_OFF 0
#define VS_OFF (64 * KS_STRIDE)
#define PS_OFF (VS_OFF + 64 * VS_STRIDE)
#define PS_WARP (16 * PS_STRIDE)
#define SMEM_WORDS (PS_OFF + 8 * PS_WARP)

__global__ __launch_bounds__(256) void flash_tc_kernel(
    const float* __restrict__ Q, const float* __restrict__ K,
    const float* __restrict__ V, const unsigned* __restrict__ Mb,
    float* __restrict__ O)
{
    extern __shared__ uint32_t sm[];
    uint32_t* Ks = sm + KS_OFF;
    uint32_t* Vs = sm + VS_OFF;

    const int t    = threadIdx.x;
    const int lane = t & 31;
    const int w    = t >> 5;
    const int g    = lane >> 2;    // group id (row within fragment)
    const int tig  = lane & 3;     // thread in group
    uint32_t* Psw  = sm + PS_OFF + w * PS_WARP;

    const int q0 = blockIdx.x * 128;
    const int h  = blockIdx.y;
    const int b  = blockIdx.z;
    const int rw = q0 + w * 16;    // warp's first q row

    const float* Qb = Q + ((size_t)(b * H_ + h) * SL + rw) * HD;
    const float* Kb = K + (size_t)(b * H_ + h) * SL * HD;
    const float* Vb = V + (size_t)(b * H_ + h) * SL * HD;

    // ---- stage this warp's Q tile (16x64) into Psw, tf32-rounded ----
    #pragma unroll
    for (int i = 0; i < 8; i++) {
        int f  = lane + i * 32;
        int r  = f >> 4;
        int c4 = (f & 15) << 2;
        float4 qv = *(const float4*)(Qb + r * HD + c4);
        uint4 uq = { f2tf32(qv.x), f2tf32(qv.y), f2tf32(qv.z), f2tf32(qv.w) };
        *(uint4*)(Psw + r * PS_STRIDE + c4) = uq;
    }
    __syncwarp();

    // ---- Q A-fragments for all 8 k-blocks, kept in registers ----
    uint32_t qa[8][4];
    #pragma unroll
    for (int kt = 0; kt < 8; kt++) {
        qa[kt][0] = Psw[g * PS_STRIDE + kt * 8 + tig];
        qa[kt][1] = Psw[(g + 8) * PS_STRIDE + kt * 8 + tig];
        qa[kt][2] = Psw[g * PS_STRIDE + kt * 8 + tig + 4];
        qa[kt][3] = Psw[(g + 8) * PS_STRIDE + kt * 8 + tig + 4];
    }

    float oacc[8][4];
    #pragma unroll
    for (int nt = 0; nt < 8; nt++)
        #pragma unroll
        for (int e = 0; e < 4; e++) oacc[nt][e] = 0.0f;

    float rm0 = -3.0e38f, rm1 = -3.0e38f, rl0 = 0.0f, rl1 = 0.0f;

    const unsigned* Mr0 = Mb + (size_t)(rw + g) * 128;
    const unsigned* Mr1 = Mb + (size_t)(rw + g + 8) * 128;

    for (int kbi = 0; kbi < SL / 64; kbi++) {
        const int kb = kbi * 64;
        __syncthreads();
        // ---- cooperative K/V tile load (tf32-rounded) ----
        #pragma unroll
        for (int i = 0; i < 4; i++) {
            int f  = t + i * 256;
            int r  = f >> 4;
            int c4 = (f & 15) << 2;
            float4 kv = *(const float4*)(Kb + (size_t)(kb + r) * HD + c4);
            uint4 uk = { f2tf32(kv.x), f2tf32(kv.y), f2tf32(kv.z), f2tf32(kv.w) };
            *(uint4*)(Ks + r * KS_STRIDE + c4) = uk;
            float4 vv = *(const float4*)(Vb + (size_t)(kb + r) * HD + c4);
            uint4 uv = { f2tf32(vv.x), f2tf32(vv.y), f2tf32(vv.z), f2tf32(vv.w) };
            *(uint4*)(Vs + r * VS_STRIDE + c4) = uv;
        }
        __syncthreads();

        // ---- mask bits for this warp's two fragment rows ----
        uint2 mw0 = *(const uint2*)(Mr0 + kbi * 2);
        uint2 mw1 = *(const uint2*)(Mr1 + kbi * 2);

        // ---- S = Q K^T ----
        float s[8][4];
        #pragma unroll
        for (int nt = 0; nt < 8; nt++) {
            s[nt][0] = 0.0f; s[nt][1] = 0.0f; s[nt][2] = 0.0f; s[nt][3] = 0.0f;
            #pragma unroll
            for (int kt = 0; kt < 8; kt++) {
                uint32_t b0 = Ks[(nt * 8 + g) * KS_STRIDE + kt * 8 + tig];
                uint32_t b1 = Ks[(nt * 8 + g) * KS_STRIDE + kt * 8 + tig + 4];
                mma_tf32(s[nt], qa[kt], b0, b1);
            }
        }

        // ---- masking (-1e9 to match reference) ----
        #pragma unroll
        for (int nt = 0; nt < 8; nt++) {
            unsigned w0 = (nt < 4) ? mw0.x : mw0.y;
            unsigned w1 = (nt < 4) ? mw1.x : mw1.y;
            int sh = (nt & 3) * 8 + 2 * tig;
            if (!((w0 >> sh) & 1))       s[nt][0] = -1e9f;
            if (!((w0 >> (sh + 1)) & 1)) s[nt][1] = -1e9f;
            if (!((w1 >> sh) & 1))       s[nt][2] = -1e9f;
            if (!((w1 >> (sh + 1)) & 1)) s[nt][3] = -1e9f;
        }

        // ---- online softmax (rows g and g+8) ----
        float m0 = -3.0e38f, m1 = -3.0e38f;
        #pragma unroll
        for (int nt = 0; nt < 8; nt++) {
            m0 = fmaxf(m0, fmaxf(s[nt][0], s[nt][1]));
            m1 = fmaxf(m1, fmaxf(s[nt][2], s[nt][3]));
        }
        m0 = fmaxf(m0, __shfl_xor_sync(0xffffffffu, m0, 1));
        m0 = fmaxf(m0, __shfl_xor_sync(0xffffffffu, m0, 2));
        m1 = fmaxf(m1, __shfl_xor_sync(0xffffffffu, m1, 1));
        m1 = fmaxf(m1, __shfl_xor_sync(0xffffffffu, m1, 2));

        float nm0 = fmaxf(rm0, m0), nm1 = fmaxf(rm1, m1);
        float corr0 = __expf(rm0 - nm0), corr1 = __expf(rm1 - nm1);

        float pl0 = 0.0f, pl1 = 0.0f;
        #pragma unroll
        for (int nt = 0; nt < 8; nt++) {
            s[nt][0] = __expf(s[nt][0] - nm0);
            s[nt][1] = __expf(s[nt][1] - nm0);
            s[nt][2] = __expf(s[nt][2] - nm1);
            s[nt][3] = __expf(s[nt][3] - nm1);
            pl0 += s[nt][0] + s[nt][1];
            pl1 += s[nt][2] + s[nt][3];
        }
        pl0 += __shfl_xor_sync(0xffffffffu, pl0, 1);
        pl0 += __shfl_xor_sync(0xffffffffu, pl0, 2);
        pl1 += __shfl_xor_sync(0xffffffffu, pl1, 1);
        pl1 += __shfl_xor_sync(0xffffffffu, pl1, 2);

        rl0 = rl0 * corr0 + pl0;  rm0 = nm0;
        rl1 = rl1 * corr1 + pl1;  rm1 = nm1;

        #pragma unroll
        for (int nt = 0; nt < 8; nt++) {
            oacc[nt][0] *= corr0; oacc[nt][1] *= corr0;
            oacc[nt][2] *= corr1; oacc[nt][3] *= corr1;
        }

        // ---- store P (tf32) to warp-private smem ----
        #pragma unroll
        for (int nt = 0; nt < 8; nt++) {
            uint2 p0 = { f2tf32(s[nt][0]), f2tf32(s[nt][1]) };
            uint2 p1 = { f2tf32(s[nt][2]), f2tf32(s[nt][3]) };
            *(uint2*)(Psw + g * PS_STRIDE + nt * 8 + 2 * tig) = p0;
            *(uint2*)(Psw + (g + 8) * PS_STRIDE + nt * 8 + 2 * tig) = p1;
        }
        __syncwarp();

        // ---- O += P V ----
        #pragma unroll
        for (int kt = 0; kt < 8; kt++) {
            uint32_t pa[4];
            pa[0] = Psw[g * PS_STRIDE + kt * 8 + tig];
            pa[1] = Psw[(g + 8) * PS_STRIDE + kt * 8 + tig];
            pa[2] = Psw[g * PS_STRIDE + kt * 8 + tig + 4];
            pa[3] = Psw[(g + 8) * PS_STRIDE + kt * 8 + tig + 4];
            #pragma unroll
            for (int nt = 0; nt < 8; nt++) {
                uint32_t b0 = Vs[(kt * 8 + tig) * VS_STRIDE + nt * 8 + g];
                uint32_t b1 = Vs[(kt * 8 + tig + 4) * VS_STRIDE + nt * 8 + g];
                mma_tf32(oacc[nt], pa, b0, b1);
            }
        }
        __syncwarp();   // protect Psw before next tile's stores
    }

    // ---- normalize + store [B,S,256] head-concat ----
    float inv0 = 1.0f / rl0, inv1 = 1.0f / rl1;
    float* Ob = O + ((size_t)b * SL + rw) * D_ + h * HD;
    #pragma unroll
    for (int nt = 0; nt < 8; nt++) {
        int col = nt * 8 + 2 * tig;
        float2 o0 = { oacc[nt][0] * inv0, oacc[nt][1] * inv0 };
        float2 o1 = { oacc[nt][2] * inv1, oacc[nt][3] * inv1 };
        *(float2*)(Ob + (size_t)g * D_ + col) = o0;
        *(float2*)(Ob + (size_t)(g + 8) * D_ + col) = o1;
    }
}

// ---------------------------------------------------------------------------
extern "C" void kernel_launch(void* const* d_in, const int* in_sizes, int n_in,
                              void* d_out, int out_size)
{
    const float* x_logic  = (const float*)d_in[0];
    const float* x_memory = (const float*)d_in[1];
    const int*   mask     = (const int*)  d_in[2];
    const float* Wq = (const float*)d_in[3];
    const float* bq = (const float*)d_in[4];
    const float* Wk = (const float*)d_in[5];
    const float* bk = (const float*)d_in[6];
    const float* Wv = (const float*)d_in[7];
    const float* bv = (const float*)d_in[8];
    const float* Wo = (const float*)d_in[9];
    const float* bo = (const float*)d_in[10];
    float* out = (float*)d_out;

    float *gQ, *gK, *gV, *gA; unsigned* gM;
    cudaGetSymbolAddress((void**)&gQ, g_Q);
    cudaGetSymbolAddress((void**)&gK, g_K);
    cudaGetSymbolAddress((void**)&gV, g_V);
    cudaGetSymbolAddress((void**)&gA, g_AT);
    cudaGetSymbolAddress((void**)&gM, g_M);

    const int M = B_ * SL;            // 8192
    dim3 gg(M / 64, D_ / 64);         // 128 x 4

    mask_pack_kernel<<<SL * SL / 32 / 256, 256>>>(mask, gM);

    // Q gets the 1/sqrt(head_dim)=0.125 scale folded into its projection.
    gemm_kernel<1><<<gg, 256>>>(x_logic,  Wq, bq, gQ, 0.125f);
    gemm_kernel<1><<<gg, 256>>>(x_logic,  Wk, bk, gK, 1.0f);
    gemm_kernel<1><<<gg, 256>>>(x_memory, Wv, bv, gV, 1.0f);

    const int smem_bytes = SMEM_WORDS * (int)sizeof(uint32_t);  // 70656
    cudaFuncSetAttribute(flash_tc_kernel,
                         cudaFuncAttributeMaxDynamicSharedMemorySize, smem_bytes);
    dim3 ga(SL / 128, H_, B_);        // 32 x 4 x 2 = 256 blocks
    flash_tc_kernel<<<ga, 256, smem_bytes>>>(gQ, gK, gV, gM, gA);

    gemm_kernel<0><<<gg, 256>>>(gA, Wo, bo, out, 1.0f);
}

// round 5
// speedup vs baseline: 3.7604x; 1.4271x over previous
#include <cuda_runtime.h>
#include <cstdint>

// Problem constants
#define B_  2
#define H_  4
#define SL  4096
#define D_  256
#define HD  64

// Scratch (allocation-free rule: __device__ globals)
__device__ float    g_Q[B_ * H_ * SL * HD];   // [B,H,S,64], pre-scaled by 1/8
__device__ float    g_K[B_ * H_ * SL * HD];
__device__ float    g_V[B_ * H_ * SL * HD];
__device__ float    g_AT[B_ * SL * D_];       // attention output [B,S,256]
__device__ unsigned g_M[SL * SL / 32];        // packed mask bits

// ---------------------------------------------------------------------------
// helpers
// ---------------------------------------------------------------------------
__device__ __forceinline__ uint32_t f2tf32(float x) {
    uint32_t u;
    asm("cvt.rna.tf32.f32 %0, %1;" : "=r"(u) : "f"(x));
    return u;
}

__device__ __forceinline__ void mma_tf32(float d[4], const uint32_t a[4],
                                         uint32_t b0, uint32_t b1) {
    asm volatile(
        "mma.sync.aligned.m16n8k8.row.col.f32.tf32.tf32.f32 "
        "{%0,%1,%2,%3}, {%4,%5,%6,%7}, {%8,%9}, {%0,%1,%2,%3};"
        : "+f"(d[0]), "+f"(d[1]), "+f"(d[2]), "+f"(d[3])
        : "r"(a[0]), "r"(a[1]), "r"(a[2]), "r"(a[3]), "r"(b0), "r"(b1));
}

__device__ __forceinline__ void cp16(uint32_t saddr, const void* g) {
    asm volatile("cp.async.ca.shared.global [%0], [%1], 16;"
                 :: "r"(saddr), "l"(g));
}
__device__ __forceinline__ void cp_commit() {
    asm volatile("cp.async.commit_group;");
}
template <int N>
__device__ __forceinline__ void cp_wait() {
    asm volatile("cp.async.wait_group %0;" :: "n"(N));
}

// ---------------------------------------------------------------------------
// Pack int32 mask [S,S] into bitmask (1 bit/element).
// ---------------------------------------------------------------------------
__global__ __launch_bounds__(256) void mask_pack_kernel(
    const int* __restrict__ mask, unsigned* __restrict__ out)
{
    int idx = blockIdx.x * 256 + threadIdx.x;
    const int* p = mask + (size_t)idx * 32;
    unsigned w = 0;
    #pragma unroll
    for (int i = 0; i < 32; i += 4) {
        int4 v = *(const int4*)(p + i);
        if (v.x) w |= 1u << i;
        if (v.y) w |= 1u << (i + 1);
        if (v.z) w |= 1u << (i + 2);
        if (v.w) w |= 1u << (i + 3);
    }
    out[idx] = w;
}

// ---------------------------------------------------------------------------
// tf32 tensor-core GEMM: C = (A @ W^T + bias) * outScale
//   A [M,256], W [256,256] (torch Linear layout), 128x64 tile, BK=64.
//   8 warps; warp w owns rows w*16..w*16+15, all 64 cols.
//   MODE 0: C row-major [M,256]; MODE 1: C as [B,H,S,64] (blockIdx.y = head)
// ---------------------------------------------------------------------------
#define GA_STRIDE 68
#define GW_STRIDE 68
#define GA_WORDS (128 * GA_STRIDE)
#define GW_WORDS (64 * GW_STRIDE)
#define GEMM_SMEM_BYTES ((GA_WORDS + GW_WORDS) * 4)

template <int MODE>
__global__ __launch_bounds__(256) void gemm_tc_kernel(
    const float* __restrict__ A, const float* __restrict__ W,
    const float* __restrict__ bias, float* __restrict__ C, float outScale)
{
    extern __shared__ uint32_t smg[];
    uint32_t* As = smg;
    uint32_t* Ws = smg + GA_WORDS;

    const int t    = threadIdx.x;
    const int lane = t & 31;
    const int w    = t >> 5;
    const int g    = lane >> 2;
    const int tig  = lane & 3;
    const int rw   = w * 16;

    const int m0 = blockIdx.x * 128, n0 = blockIdx.y * 64;

    float acc[8][4];
    #pragma unroll
    for (int nt = 0; nt < 8; nt++)
        #pragma unroll
        for (int e = 0; e < 4; e++) acc[nt][e] = 0.0f;

    for (int k0 = 0; k0 < 256; k0 += 64) {
        __syncthreads();
        // stage A tile 128x64 (tf32 rna)
        #pragma unroll
        for (int i = 0; i < 8; i++) {
            int f  = t + i * 256;
            int r  = f >> 4;
            int c4 = (f & 15) << 2;
            float4 av = *(const float4*)(A + (size_t)(m0 + r) * 256 + k0 + c4);
            uint4 ua = { f2tf32(av.x), f2tf32(av.y), f2tf32(av.z), f2tf32(av.w) };
            *(uint4*)(As + r * GA_STRIDE + c4) = ua;
        }
        // stage W tile 64x64
        #pragma unroll
        for (int i = 0; i < 4; i++) {
            int f  = t + i * 256;
            int r  = f >> 4;
            int c4 = (f & 15) << 2;
            float4 wv = *(const float4*)(W + (size_t)(n0 + r) * 256 + k0 + c4);
            uint4 uw = { f2tf32(wv.x), f2tf32(wv.y), f2tf32(wv.z), f2tf32(wv.w) };
            *(uint4*)(Ws + r * GW_STRIDE + c4) = uw;
        }
        __syncthreads();

        // preload a-fragments for the 8 k-blocks
        uint32_t af[8][4];
        #pragma unroll
        for (int kt = 0; kt < 8; kt++) {
            af[kt][0] = As[(rw + g) * GA_STRIDE + kt * 8 + tig];
            af[kt][1] = As[(rw + g + 8) * GA_STRIDE + kt * 8 + tig];
            af[kt][2] = As[(rw + g) * GA_STRIDE + kt * 8 + tig + 4];
            af[kt][3] = As[(rw + g + 8) * GA_STRIDE + kt * 8 + tig + 4];
        }
        #pragma unroll
        for (int nt = 0; nt < 8; nt++) {
            #pragma unroll
            for (int kt = 0; kt < 8; kt++) {
                uint32_t b0 = Ws[(nt * 8 + g) * GW_STRIDE + kt * 8 + tig];
                uint32_t b1 = Ws[(nt * 8 + g) * GW_STRIDE + kt * 8 + tig + 4];
                mma_tf32(acc[nt], af[kt], b0, b1);
            }
        }
    }

    // epilogue
    const int r0 = m0 + rw + g;
    const int r1 = r0 + 8;
    #pragma unroll
    for (int nt = 0; nt < 8; nt++) {
        int col = nt * 8 + 2 * tig;
        float bi0 = __ldg(bias + n0 + col);
        float bi1 = __ldg(bias + n0 + col + 1);
        float2 o0 = { (acc[nt][0] + bi0) * outScale, (acc[nt][1] + bi1) * outScale };
        float2 o1 = { (acc[nt][2] + bi0) * outScale, (acc[nt][3] + bi1) * outScale };
        if (MODE == 0) {
            *(float2*)(C + (size_t)r0 * 256 + n0 + col) = o0;
            *(float2*)(C + (size_t)r1 * 256 + n0 + col) = o1;
        } else {
            int bb0 = r0 >> 12, s0 = r0 & (SL - 1);
            int bb1 = r1 >> 12, s1 = r1 & (SL - 1);
            *(float2*)(C + ((size_t)(bb0 * H_ + blockIdx.y) * SL + s0) * HD + col) = o0;
            *(float2*)(C + ((size_t)(bb1 * H_ + blockIdx.y) * SL + s1) * HD + col) = o1;
        }
    }
}

// ---------------------------------------------------------------------------
// Flash attention, tf32 mma, double-buffered K/V via cp.async.
// Block: 8 warps, 128 q-rows. Key tile = 64.
// K/V land as raw fp32 bits; tf32 MMA uses the truncated mantissa.
// ---------------------------------------------------------------------------
#define KS_STRIDE 68
#define VS_STRIDE 72
#define PS_STRIDE 68
#define KS_TILE (64 * KS_STRIDE)
#define VS_TILE (64 * VS_STRIDE)
#define KS_OFF 0
#define VS_OFF (2 * KS_TILE)
#define PS_OFF (VS_OFF + 2 * VS_TILE)
#define PS_WARP (16 * PS_STRIDE)
#define SMEM_WORDS (PS_OFF + 8 * PS_WARP)
#define NTILES (SL / 64)

__global__ __launch_bounds__(256) void flash_tc_kernel(
    const float* __restrict__ Q, const float* __restrict__ K,
    const float* __restrict__ V, const unsigned* __restrict__ Mb,
    float* __restrict__ O)
{
    extern __shared__ uint32_t sm[];

    const int t    = threadIdx.x;
    const int lane = t & 31;
    const int w    = t >> 5;
    const int g    = lane >> 2;
    const int tig  = lane & 3;
    uint32_t* Psw  = sm + PS_OFF + w * PS_WARP;

    const int q0 = blockIdx.x * 128;
    const int h  = blockIdx.y;
    const int b  = blockIdx.z;
    const int rw = q0 + w * 16;

    const float* Qb = Q + ((size_t)(b * H_ + h) * SL + rw) * HD;
    const float* Kb = K + (size_t)(b * H_ + h) * SL * HD;
    const float* Vb = V + (size_t)(b * H_ + h) * SL * HD;

    const uint32_t smem_u32 = (uint32_t)__cvta_generic_to_shared(sm);

    // per-thread cp.async slice: 4 chunks of K + 4 of V per tile
    int cr[4], cc[4];
    #pragma unroll
    for (int i = 0; i < 4; i++) {
        int f = t + i * 256;
        cr[i] = f >> 4;
        cc[i] = (f & 15) << 2;
    }

    // ---- prologue: issue tile 0 ----
    #pragma unroll
    for (int i = 0; i < 4; i++) {
        cp16(smem_u32 + (KS_OFF + cr[i] * KS_STRIDE + cc[i]) * 4,
             Kb + (size_t)cr[i] * HD + cc[i]);
        cp16(smem_u32 + (VS_OFF + cr[i] * VS_STRIDE + cc[i]) * 4,
             Vb + (size_t)cr[i] * HD + cc[i]);
    }
    cp_commit();

    // ---- stage this warp's Q tile (16x64) into Psw, tf32-rna ----
    #pragma unroll
    for (int i = 0; i < 8; i++) {
        int f  = lane + i * 32;
        int r  = f >> 4;
        int c4 = (f & 15) << 2;
        float4 qv = *(const float4*)(Qb + r * HD + c4);
        uint4 uq = { f2tf32(qv.x), f2tf32(qv.y), f2tf32(qv.z), f2tf32(qv.w) };
        *(uint4*)(Psw + r * PS_STRIDE + c4) = uq;
    }
    __syncwarp();

    uint32_t qa[8][4];
    #pragma unroll
    for (int kt = 0; kt < 8; kt++) {
        qa[kt][0] = Psw[g * PS_STRIDE + kt * 8 + tig];
        qa[kt][1] = Psw[(g + 8) * PS_STRIDE + kt * 8 + tig];
        qa[kt][2] = Psw[g * PS_STRIDE + kt * 8 + tig + 4];
        qa[kt][3] = Psw[(g + 8) * PS_STRIDE + kt * 8 + tig + 4];
    }

    float oacc[8][4];
    #pragma unroll
    for (int nt = 0; nt < 8; nt++)
        #pragma unroll
        for (int e = 0; e < 4; e++) oacc[nt][e] = 0.0f;

    float rm0 = -3.0e38f, rm1 = -3.0e38f, rl0 = 0.0f, rl1 = 0.0f;

    const unsigned* Mr0 = Mb + (size_t)(rw + g) * 128;
    const unsigned* Mr1 = Mb + (size_t)(rw + g + 8) * 128;

    for (int kbi = 0; kbi < NTILES; kbi++) {
        const int cur = kbi & 1;
        uint32_t* Ks = sm + KS_OFF + cur * KS_TILE;
        uint32_t* Vs = sm + VS_OFF + cur * VS_TILE;

        __syncthreads();   // everyone done computing tile kbi-1 (frees !cur bufs)
        if (kbi + 1 < NTILES) {
            const int nxt = (kbi + 1) & 1;
            const size_t gofs = (size_t)(kbi + 1) * 64 * HD;
            #pragma unroll
            for (int i = 0; i < 4; i++) {
                cp16(smem_u32 + (KS_OFF + nxt * KS_TILE + cr[i] * KS_STRIDE + cc[i]) * 4,
                     Kb + gofs + (size_t)cr[i] * HD + cc[i]);
                cp16(smem_u32 + (VS_OFF + nxt * VS_TILE + cr[i] * VS_STRIDE + cc[i]) * 4,
                     Vb + gofs + (size_t)cr[i] * HD + cc[i]);
            }
            cp_commit();
            cp_wait<1>();
        } else {
            cp_wait<0>();
        }
        __syncthreads();   // tile kbi visible to all

        uint2 mw0 = *(const uint2*)(Mr0 + kbi * 2);
        uint2 mw1 = *(const uint2*)(Mr1 + kbi * 2);

        // ---- S = Q K^T ----
        float s[8][4];
        #pragma unroll
        for (int nt = 0; nt < 8; nt++) {
            s[nt][0] = 0.0f; s[nt][1] = 0.0f; s[nt][2] = 0.0f; s[nt][3] = 0.0f;
            #pragma unroll
            for (int kt = 0; kt < 8; kt++) {
                uint32_t b0 = Ks[(nt * 8 + g) * KS_STRIDE + kt * 8 + tig];
                uint32_t b1 = Ks[(nt * 8 + g) * KS_STRIDE + kt * 8 + tig + 4];
                mma_tf32(s[nt], qa[kt], b0, b1);
            }
        }

        // ---- masking (-1e9 to match reference) ----
        #pragma unroll
        for (int nt = 0; nt < 8; nt++) {
            unsigned w0 = (nt < 4) ? mw0.x : mw0.y;
            unsigned w1 = (nt < 4) ? mw1.x : mw1.y;
            int sh = (nt & 3) * 8 + 2 * tig;
            if (!((w0 >> sh) & 1))       s[nt][0] = -1e9f;
            if (!((w0 >> (sh + 1)) & 1)) s[nt][1] = -1e9f;
            if (!((w1 >> sh) & 1))       s[nt][2] = -1e9f;
            if (!((w1 >> (sh + 1)) & 1)) s[nt][3] = -1e9f;
        }

        // ---- online softmax ----
        float m0 = -3.0e38f, m1 = -3.0e38f;
        #pragma unroll
        for (int nt = 0; nt < 8; nt++) {
            m0 = fmaxf(m0, fmaxf(s[nt][0], s[nt][1]));
            m1 = fmaxf(m1, fmaxf(s[nt][2], s[nt][3]));
        }
        m0 = fmaxf(m0, __shfl_xor_sync(0xffffffffu, m0, 1));
        m0 = fmaxf(m0, __shfl_xor_sync(0xffffffffu, m0, 2));
        m1 = fmaxf(m1, __shfl_xor_sync(0xffffffffu, m1, 1));
        m1 = fmaxf(m1, __shfl_xor_sync(0xffffffffu, m1, 2));

        float nm0 = fmaxf(rm0, m0), nm1 = fmaxf(rm1, m1);
        float corr0 = __expf(rm0 - nm0), corr1 = __expf(rm1 - nm1);

        float pl0 = 0.0f, pl1 = 0.0f;
        #pragma unroll
        for (int nt = 0; nt < 8; nt++) {
            s[nt][0] = __expf(s[nt][0] - nm0);
            s[nt][1] = __expf(s[nt][1] - nm0);
            s[nt][2] = __expf(s[nt][2] - nm1);
            s[nt][3] = __expf(s[nt][3] - nm1);
            pl0 += s[nt][0] + s[nt][1];
            pl1 += s[nt][2] + s[nt][3];
        }
        pl0 += __shfl_xor_sync(0xffffffffu, pl0, 1);
        pl0 += __shfl_xor_sync(0xffffffffu, pl0, 2);
        pl1 += __shfl_xor_sync(0xffffffffu, pl1, 1);
        pl1 += __shfl_xor_sync(0xffffffffu, pl1, 2);

        rl0 = rl0 * corr0 + pl0;  rm0 = nm0;
        rl1 = rl1 * corr1 + pl1;  rm1 = nm1;

        #pragma unroll
        for (int nt = 0; nt < 8; nt++) {
            oacc[nt][0] *= corr0; oacc[nt][1] *= corr0;
            oacc[nt][2] *= corr1; oacc[nt][3] *= corr1;
        }

        // ---- store P (tf32) to warp-private smem ----
        #pragma unroll
        for (int nt = 0; nt < 8; nt++) {
            uint2 p0 = { f2tf32(s[nt][0]), f2tf32(s[nt][1]) };
            uint2 p1 = { f2tf32(s[nt][2]), f2tf32(s[nt][3]) };
            *(uint2*)(Psw + g * PS_STRIDE + nt * 8 + 2 * tig) = p0;
            *(uint2*)(Psw + (g + 8) * PS_STRIDE + nt * 8 + 2 * tig) = p1;
        }
        __syncwarp();

        // ---- O += P V ----
        #pragma unroll
        for (int kt = 0; kt < 8; kt++) {
            uint32_t pa[4];
            pa[0] = Psw[g * PS_STRIDE + kt * 8 + tig];
            pa[1] = Psw[(g + 8) * PS_STRIDE + kt * 8 + tig];
            pa[2] = Psw[g * PS_STRIDE + kt * 8 + tig + 4];
            pa[3] = Psw[(g + 8) * PS_STRIDE + kt * 8 + tig + 4];
            #pragma unroll
            for (int nt = 0; nt < 8; nt++) {
                uint32_t b0 = Vs[(kt * 8 + tig) * VS_STRIDE + nt * 8 + g];
                uint32_t b1 = Vs[(kt * 8 + tig + 4) * VS_STRIDE + nt * 8 + g];
                mma_tf32(oacc[nt], pa, b0, b1);
            }
        }
        __syncwarp();   // protect Psw before next tile's stores
    }

    // ---- normalize + store [B,S,256] head-concat ----
    float inv0 = 1.0f / rl0, inv1 = 1.0f / rl1;
    float* Ob = O + ((size_t)b * SL + rw) * D_ + h * HD;
    #pragma unroll
    for (int nt = 0; nt < 8; nt++) {
        int col = nt * 8 + 2 * tig;
        float2 o0 = { oacc[nt][0] * inv0, oacc[nt][1] * inv0 };
        float2 o1 = { oacc[nt][2] * inv1, oacc[nt][3] * inv1 };
        *(float2*)(Ob + (size_t)g * D_ + col) = o0;
        *(float2*)(Ob + (size_t)(g + 8) * D_ + col) = o1;
    }
}

// ---------------------------------------------------------------------------
extern "C" void kernel_launch(void* const* d_in, const int* in_sizes, int n_in,
                              void* d_out, int out_size)
{
    const float* x_logic  = (const float*)d_in[0];
    const float* x_memory = (const float*)d_in[1];
    const int*   mask     = (const int*)  d_in[2];
    const float* Wq = (const float*)d_in[3];
    const float* bq = (const float*)d_in[4];
    const float* Wk = (const float*)d_in[5];
    const float* bk = (const float*)d_in[6];
    const float* Wv = (const float*)d_in[7];
    const float* bv = (const float*)d_in[8];
    const float* Wo = (const float*)d_in[9];
    const float* bo = (const float*)d_in[10];
    float* out = (float*)d_out;

    float *gQ, *gK, *gV, *gA; unsigned* gM;
    cudaGetSymbolAddress((void**)&gQ, g_Q);
    cudaGetSymbolAddress((void**)&gK, g_K);
    cudaGetSymbolAddress((void**)&gV, g_V);
    cudaGetSymbolAddress((void**)&gA, g_AT);
    cudaGetSymbolAddress((void**)&gM, g_M);

    mask_pack_kernel<<<SL * SL / 32 / 256, 256>>>(mask, gM);

    cudaFuncSetAttribute(gemm_tc_kernel<0>,
                         cudaFuncAttributeMaxDynamicSharedMemorySize, GEMM_SMEM_BYTES);
    cudaFuncSetAttribute(gemm_tc_kernel<1>,
                         cudaFuncAttributeMaxDynamicSharedMemorySize, GEMM_SMEM_BYTES);

    dim3 gg(B_ * SL / 128, D_ / 64);   // 64 x 4
    // Q gets the 1/sqrt(head_dim)=0.125 scale folded into its projection.
    gemm_tc_kernel<1><<<gg, 256, GEMM_SMEM_BYTES>>>(x_logic,  Wq, bq, gQ, 0.125f);
    gemm_tc_kernel<1><<<gg, 256, GEMM_SMEM_BYTES>>>(x_logic,  Wk, bk, gK, 1.0f);
    gemm_tc_kernel<1><<<gg, 256, GEMM_SMEM_BYTES>>>(x_memory, Wv, bv, gV, 1.0f);

    const int smem_bytes = SMEM_WORDS * (int)sizeof(uint32_t);
    cudaFuncSetAttribute(flash_tc_kernel,
                         cudaFuncAttributeMaxDynamicSharedMemorySize, smem_bytes);
    dim3 ga(SL / 128, H_, B_);        // 32 x 4 x 2 = 256 blocks
    flash_tc_kernel<<<ga, 256, smem_bytes>>>(gQ, gK, gV, gM, gA);

    gemm_tc_kernel<0><<<gg, 256, GEMM_SMEM_BYTES>>>(gA, Wo, bo, out, 1.0f);
}

// round 7
// speedup vs baseline: 4.0868x; 1.0868x over previous
#include <cuda_runtime.h>
#include <cstdint>

// Problem constants
#define B_  2
#define H_  4
#define SL  4096
#define D_  256
#define HD  64

// Scratch (allocation-free rule: __device__ globals)
__device__ float    g_Q[B_ * H_ * SL * HD];   // [B,H,S,64], pre-scaled, tf32-rounded
__device__ float    g_K[B_ * H_ * SL * HD];   // tf32-rounded
__device__ float    g_V[B_ * H_ * SL * HD];   // tf32-rounded
__device__ float    g_AT[B_ * SL * D_];       // attention output [B,S,256]
__device__ unsigned g_M[SL * SL / 32];        // packed mask bits

// ---------------------------------------------------------------------------
// helpers
// ---------------------------------------------------------------------------
__device__ __forceinline__ uint32_t f2tf32(float x) {
    uint32_t u;
    asm("cvt.rna.tf32.f32 %0, %1;" : "=r"(u) : "f"(x));
    return u;
}

__device__ __forceinline__ void mma_tf32(float d[4], const uint32_t a[4],
                                         uint32_t b0, uint32_t b1) {
    asm volatile(
        "mma.sync.aligned.m16n8k8.row.col.f32.tf32.tf32.f32 "
        "{%0,%1,%2,%3}, {%4,%5,%6,%7}, {%8,%9}, {%0,%1,%2,%3};"
        : "+f"(d[0]), "+f"(d[1]), "+f"(d[2]), "+f"(d[3])
        : "r"(a[0]), "r"(a[1]), "r"(a[2]), "r"(a[3]), "r"(b0), "r"(b1));
}

__device__ __forceinline__ void cp16(uint32_t saddr, const void* g) {
    asm volatile("cp.async.ca.shared.global [%0], [%1], 16;"
                 :: "r"(saddr), "l"(g));
}
__device__ __forceinline__ void cp_commit() {
    asm volatile("cp.async.commit_group;");
}
template <int N>
__device__ __forceinline__ void cp_wait() {
    asm volatile("cp.async.wait_group %0;" :: "n"(N));
}

// ---------------------------------------------------------------------------
// Pack int32 mask [S,S] into bitmask (1 bit/element).
// ---------------------------------------------------------------------------
__global__ __launch_bounds__(256) void mask_pack_kernel(
    const int* __restrict__ mask, unsigned* __restrict__ out)
{
    int idx = blockIdx.x * 256 + threadIdx.x;
    const int* p = mask + (size_t)idx * 32;
    unsigned w = 0;
    #pragma unroll
    for (int i = 0; i < 32; i += 4) {
        int4 v = *(const int4*)(p + i);
        if (v.x) w |= 1u << i;
        if (v.y) w |= 1u << (i + 1);
        if (v.z) w |= 1u << (i + 2);
        if (v.w) w |= 1u << (i + 3);
    }
    out[idx] = w;
}

// ---------------------------------------------------------------------------
// Shared GEMM core: 128x64 tile, BK=64, tf32 mma, A-prefetch pipeline.
// ---------------------------------------------------------------------------
#define GA_STRIDE 68
#define GW_STRIDE 68
#define GA_WORDS (128 * GA_STRIDE)
#define GW_WORDS (64 * GW_STRIDE)
#define GEMM_SMEM_BYTES ((GA_WORDS + GW_WORDS) * 4)

struct GemmCtx {
    int t, lane, w, g, tig, rw;
};

__device__ __forceinline__ void gemm_core(
    uint32_t* As, uint32_t* Ws,
    const float* __restrict__ A, const float* __restrict__ W,
    int m0, int n0, const GemmCtx& cx, float acc[8][4])
{
    const int t = cx.t;

    // prologue: prefetch k-step 0 A rows into registers
    float4 ra[8];
    #pragma unroll
    for (int i = 0; i < 8; i++) {
        int f  = t + i * 256;
        int r  = f >> 4;
        int c4 = (f & 15) << 2;
        ra[i] = *(const float4*)(A + (size_t)(m0 + r) * 256 + c4);
    }

    #pragma unroll
    for (int ks = 0; ks < 4; ks++) {
        const int k0 = ks * 64;
        __syncthreads();                 // prior MMA done reading smem
        // store prefetched A (tf32 rna)
        #pragma unroll
        for (int i = 0; i < 8; i++) {
            int f  = t + i * 256;
            int r  = f >> 4;
            int c4 = (f & 15) << 2;
            uint4 ua = { f2tf32(ra[i].x), f2tf32(ra[i].y),
                         f2tf32(ra[i].z), f2tf32(ra[i].w) };
            *(uint4*)(As + r * GA_STRIDE + c4) = ua;
        }
        // stage W tile 64x64 (L2-hot after first wave)
        #pragma unroll
        for (int i = 0; i < 4; i++) {
            int f  = t + i * 256;
            int r  = f >> 4;
            int c4 = (f & 15) << 2;
            float4 wv = *(const float4*)(W + (size_t)(n0 + r) * 256 + k0 + c4);
            uint4 uw = { f2tf32(wv.x), f2tf32(wv.y), f2tf32(wv.z), f2tf32(wv.w) };
            *(uint4*)(Ws + r * GW_STRIDE + c4) = uw;
        }
        __syncthreads();

        // prefetch NEXT k-step's A rows (LDG in flight during the MMAs)
        if (ks < 3) {
            #pragma unroll
            for (int i = 0; i < 8; i++) {
                int f  = t + i * 256;
                int r  = f >> 4;
                int c4 = (f & 15) << 2;
                ra[i] = *(const float4*)(A + (size_t)(m0 + r) * 256 + k0 + 64 + c4);
            }
        }

        // a-fragments
        uint32_t af[8][4];
        #pragma unroll
        for (int kt = 0; kt < 8; kt++) {
            af[kt][0] = As[(cx.rw + cx.g) * GA_STRIDE + kt * 8 + cx.tig];
            af[kt][1] = As[(cx.rw + cx.g + 8) * GA_STRIDE + kt * 8 + cx.tig];
            af[kt][2] = As[(cx.rw + cx.g) * GA_STRIDE + kt * 8 + cx.tig + 4];
            af[kt][3] = As[(cx.rw + cx.g + 8) * GA_STRIDE + kt * 8 + cx.tig + 4];
        }
        #pragma unroll
        for (int nt = 0; nt < 8; nt++) {
            #pragma unroll
            for (int kt = 0; kt < 8; kt++) {
                uint32_t b0 = Ws[(nt * 8 + cx.g) * GW_STRIDE + kt * 8 + cx.tig];
                uint32_t b1 = Ws[(nt * 8 + cx.g) * GW_STRIDE + kt * 8 + cx.tig + 4];
                mma_tf32(acc[nt], af[kt], b0, b1);
            }
        }
    }
}

// ---------------------------------------------------------------------------
// Fused Q/K/V projection: grid (64, 4, 3); z selects {Q,K,V}.
// Output [B,H,S,64], tf32-rna-rounded so flash's raw cp.async is lossless.
// ---------------------------------------------------------------------------
__global__ __launch_bounds__(256, 2) void gemm_qkv_kernel(
    const float* __restrict__ xl, const float* __restrict__ xm,
    const float* __restrict__ Wq, const float* __restrict__ bq,
    const float* __restrict__ Wk, const float* __restrict__ bk,
    const float* __restrict__ Wv, const float* __restrict__ bv,
    float* __restrict__ Cq, float* __restrict__ Ck, float* __restrict__ Cv)
{
    extern __shared__ uint32_t smg[];
    uint32_t* As = smg;
    uint32_t* Ws = smg + GA_WORDS;

    const int z = blockIdx.z;
    const float* A    = (z == 2) ? xm : xl;
    const float* W    = (z == 0) ? Wq : (z == 1) ? Wk : Wv;
    const float* bias = (z == 0) ? bq : (z == 1) ? bk : bv;
    float*       C    = (z == 0) ? Cq : (z == 1) ? Ck : Cv;
    const float outScale = (z == 0) ? 0.125f : 1.0f;

    GemmCtx cx;
    cx.t = threadIdx.x; cx.lane = cx.t & 31; cx.w = cx.t >> 5;
    cx.g = cx.lane >> 2; cx.tig = cx.lane & 3; cx.rw = cx.w * 16;

    const int m0 = blockIdx.x * 128, n0 = blockIdx.y * 64;

    float acc[8][4];
    #pragma unroll
    for (int nt = 0; nt < 8; nt++)
        #pragma unroll
        for (int e = 0; e < 4; e++) acc[nt][e] = 0.0f;

    gemm_core(As, Ws, A, W, m0, n0, cx, acc);

    // epilogue: bias, scale, tf32-rna round, store as [B,H,S,64]
    const int r0 = m0 + cx.rw + cx.g;
    const int r1 = r0 + 8;
    #pragma unroll
    for (int nt = 0; nt < 8; nt++) {
        int col = nt * 8 + 2 * cx.tig;
        float bi0 = __ldg(bias + n0 + col);
        float bi1 = __ldg(bias + n0 + col + 1);
        uint2 o0 = { f2tf32((acc[nt][0] + bi0) * outScale),
                     f2tf32((acc[nt][1] + bi1) * outScale) };
        uint2 o1 = { f2tf32((acc[nt][2] + bi0) * outScale),
                     f2tf32((acc[nt][3] + bi1) * outScale) };
        int bb0 = r0 >> 12, s0 = r0 & (SL - 1);
        int bb1 = r1 >> 12, s1 = r1 & (SL - 1);
        *(uint2*)(C + ((size_t)(bb0 * H_ + blockIdx.y) * SL + s0) * HD + col) = o0;
        *(uint2*)(C + ((size_t)(bb1 * H_ + blockIdx.y) * SL + s1) * HD + col) = o1;
    }
}

// ---------------------------------------------------------------------------
// Output GEMM: C = AT @ Wo^T + bo, row-major [M,256], fp32 out.
// ---------------------------------------------------------------------------
__global__ __launch_bounds__(256, 2) void gemm_out_kernel(
    const float* __restrict__ A, const float* __restrict__ W,
    const float* __restrict__ bias, float* __restrict__ C)
{
    extern __shared__ uint32_t smg[];
    uint32_t* As = smg;
    uint32_t* Ws = smg + GA_WORDS;

    GemmCtx cx;
    cx.t = threadIdx.x; cx.lane = cx.t & 31; cx.w = cx.t >> 5;
    cx.g = cx.lane >> 2; cx.tig = cx.lane & 3; cx.rw = cx.w * 16;

    const int m0 = blockIdx.x * 128, n0 = blockIdx.y * 64;

    float acc[8][4];
    #pragma unroll
    for (int nt = 0; nt < 8; nt++)
        #pragma unroll
        for (int e = 0; e < 4; e++) acc[nt][e] = 0.0f;

    gemm_core(As, Ws, A, W, m0, n0, cx, acc);

    const int r0 = m0 + cx.rw + cx.g;
    const int r1 = r0 + 8;
    #pragma unroll
    for (int nt = 0; nt < 8; nt++) {
        int col = nt * 8 + 2 * cx.tig;
        float bi0 = __ldg(bias + n0 + col);
        float bi1 = __ldg(bias + n0 + col + 1);
        float2 o0 = { acc[nt][0] + bi0, acc[nt][1] + bi1 };
        float2 o1 = { acc[nt][2] + bi0, acc[nt][3] + bi1 };
        *(float2*)(C + (size_t)r0 * 256 + n0 + col) = o0;
        *(float2*)(C + (size_t)r1 * 256 + n0 + col) = o1;
    }
}

// ---------------------------------------------------------------------------
// Flash attention, tf32 mma, double-buffered K/V via cp.async.
// K/V arrive as raw bits but are pre-rounded to tf32 by the projection.
// ---------------------------------------------------------------------------
#define KS_STRIDE 68
#define VS_STRIDE 72
#define PS_STRIDE 68
#define KS_TILE (64 * KS_STRIDE)
#define VS_TILE (64 * VS_STRIDE)
#define KS_OFF 0
#define VS_OFF (2 * KS_TILE)
#define PS_OFF (VS_OFF + 2 * VS_TILE)
#define PS_WARP (16 * PS_STRIDE)
#define SMEM_WORDS (PS_OFF + 8 * PS_WARP)
#define NTILES (SL / 64)

__global__ __launch_bounds__(256) void flash_tc_kernel(
    const float* __restrict__ Q, const float* __restrict__ K,
    const float* __restrict__ V, const unsigned* __restrict__ Mb,
    float* __restrict__ O)
{
    extern __shared__ uint32_t sm[];

    const int t    = threadIdx.x;
    const int lane = t & 31;
    const int w    = t >> 5;
    const int g    = lane >> 2;
    const int tig  = lane & 3;
    uint32_t* Psw  = sm + PS_OFF + w * PS_WARP;

    const int q0 = blockIdx.x * 128;
    const int h  = blockIdx.y;
    const int b  = blockIdx.z;
    const int rw = q0 + w * 16;

    const float* Qb = Q + ((size_t)(b * H_ + h) * SL + rw) * HD;
    const float* Kb = K + (size_t)(b * H_ + h) * SL * HD;
    const float* Vb = V + (size_t)(b * H_ + h) * SL * HD;

    const uint32_t smem_u32 = (uint32_t)__cvta_generic_to_shared(sm);

    int cr[4], cc[4];
    #pragma unroll
    for (int i = 0; i < 4; i++) {
        int f = t + i * 256;
        cr[i] = f >> 4;
        cc[i] = (f & 15) << 2;
    }

    // ---- prologue: issue tile 0 ----
    #pragma unroll
    for (int i = 0; i < 4; i++) {
        cp16(smem_u32 + (KS_OFF + cr[i] * KS_STRIDE + cc[i]) * 4,
             Kb + (size_t)cr[i] * HD + cc[i]);
        cp16(smem_u32 + (VS_OFF + cr[i] * VS_STRIDE + cc[i]) * 4,
             Vb + (size_t)cr[i] * HD + cc[i]);
    }
    cp_commit();

    // ---- stage this warp's Q tile (16x64) into Psw ----
    #pragma unroll
    for (int i = 0; i < 8; i++) {
        int f  = lane + i * 32;
        int r  = f >> 4;
        int c4 = (f & 15) << 2;
        float4 qv = *(const float4*)(Qb + r * HD + c4);
        uint4 uq = { f2tf32(qv.x), f2tf32(qv.y), f2tf32(qv.z), f2tf32(qv.w) };
        *(uint4*)(Psw + r * PS_STRIDE + c4) = uq;
    }
    __syncwarp();

    uint32_t qa[8][4];
    #pragma unroll
    for (int kt = 0; kt < 8; kt++) {
        qa[kt][0] = Psw[g * PS_STRIDE + kt * 8 + tig];
        qa[kt][1] = Psw[(g + 8) * PS_STRIDE + kt * 8 + tig];
        qa[kt][2] = Psw[g * PS_STRIDE + kt * 8 + tig + 4];
        qa[kt][3] = Psw[(g + 8) * PS_STRIDE + kt * 8 + tig + 4];
    }

    float oacc[8][4];
    #pragma unroll
    for (int nt = 0; nt < 8; nt++)
        #pragma unroll
        for (int e = 0; e < 4; e++) oacc[nt][e] = 0.0f;

    float rm0 = -3.0e38f, rm1 = -3.0e38f, rl0 = 0.0f, rl1 = 0.0f;

    const unsigned* Mr0 = Mb + (size_t)(rw + g) * 128;
    const unsigned* Mr1 = Mb + (size_t)(rw + g + 8) * 128;

    for (int kbi = 0; kbi < NTILES; kbi++) {
        const int cur = kbi & 1;
        uint32_t* Ks = sm + KS_OFF + cur * KS_TILE;
        uint32_t* Vs = sm + VS_OFF + cur * VS_TILE;

        __syncthreads();   // everyone done with buffer !cur
        if (kbi + 1 < NTILES) {
            const int nxt = (kbi + 1) & 1;
            const size_t gofs = (size_t)(kbi + 1) * 64 * HD;
            #pragma unroll
            for (int i = 0; i < 4; i++) {
                cp16(smem_u32 + (KS_OFF + nxt * KS_TILE + cr[i] * KS_STRIDE + cc[i]) * 4,
                     Kb + gofs + (size_t)cr[i] * HD + cc[i]);
                cp16(smem_u32 + (VS_OFF + nxt * VS_TILE + cr[i] * VS_STRIDE + cc[i]) * 4,
                     Vb + gofs + (size_t)cr[i] * HD + cc[i]);
            }
            cp_commit();
            cp_wait<1>();
        } else {
            cp_wait<0>();
        }
        __syncthreads();   // tile kbi visible

        uint2 mw0 = *(const uint2*)(Mr0 + kbi * 2);
        uint2 mw1 = *(const uint2*)(Mr1 + kbi * 2);

        // ---- S = Q K^T ----
        float s[8][4];
        #pragma unroll
        for (int nt = 0; nt < 8; nt++) {
            s[nt][0] = 0.0f; s[nt][1] = 0.0f; s[nt][2] = 0.0f; s[nt][3] = 0.0f;
            #pragma unroll
            for (int kt = 0; kt < 8; kt++) {
                uint32_t b0 = Ks[(nt * 8 + g) * KS_STRIDE + kt * 8 + tig];
                uint32_t b1 = Ks[(nt * 8 + g) * KS_STRIDE + kt * 8 + tig + 4];
                mma_tf32(s[nt], qa[kt], b0, b1);
            }
        }

        // ---- masking (-1e9 to match reference) ----
        #pragma unroll
        for (int nt = 0; nt < 8; nt++) {
            unsigned w0 = (nt < 4) ? mw0.x : mw0.y;
            unsigned w1 = (nt < 4) ? mw1.x : mw1.y;
            int sh = (nt & 3) * 8 + 2 * tig;
            if (!((w0 >> sh) & 1))       s[nt][0] = -1e9f;
            if (!((w0 >> (sh + 1)) & 1)) s[nt][1] = -1e9f;
            if (!((w1 >> sh) & 1))       s[nt][2] = -1e9f;
            if (!((w1 >> (sh + 1)) & 1)) s[nt][3] = -1e9f;
        }

        // ---- online softmax ----
        float m0 = -3.0e38f, m1 = -3.0e38f;
        #pragma unroll
        for (int nt = 0; nt < 8; nt++) {
            m0 = fmaxf(m0, fmaxf(s[nt][0], s[nt][1]));
            m1 = fmaxf(m1, fmaxf(s[nt][2], s[nt][3]));
        }
        m0 = fmaxf(m0, __shfl_xor_sync(0xffffffffu, m0, 1));
        m0 = fmaxf(m0, __shfl_xor_sync(0xffffffffu, m0, 2));
        m1 = fmaxf(m1, __shfl_xor_sync(0xffffffffu, m1, 1));
        m1 = fmaxf(m1, __shfl_xor_sync(0xffffffffu, m1, 2));

        float nm0 = fmaxf(rm0, m0), nm1 = fmaxf(rm1, m1);
        float corr0 = __expf(rm0 - nm0), corr1 = __expf(rm1 - nm1);

        float pl0 = 0.0f, pl1 = 0.0f;
        #pragma unroll
        for (int nt = 0; nt < 8; nt++) {
            s[nt][0] = __expf(s[nt][0] - nm0);
            s[nt][1] = __expf(s[nt][1] - nm0);
            s[nt][2] = __expf(s[nt][2] - nm1);
            s[nt][3] = __expf(s[nt][3] - nm1);
            pl0 += s[nt][0] + s[nt][1];
            pl1 += s[nt][2] + s[nt][3];
        }
        pl0 += __shfl_xor_sync(0xffffffffu, pl0, 1);
        pl0 += __shfl_xor_sync(0xffffffffu, pl0, 2);
        pl1 += __shfl_xor_sync(0xffffffffu, pl1, 1);
        pl1 += __shfl_xor_sync(0xffffffffu, pl1, 2);

        rl0 = rl0 * corr0 + pl0;  rm0 = nm0;
        rl1 = rl1 * corr1 + pl1;  rm1 = nm1;

        #pragma unroll
        for (int nt = 0; nt < 8; nt++) {
            oacc[nt][0] *= corr0; oacc[nt][1] *= corr0;
            oacc[nt][2] *= corr1; oacc[nt][3] *= corr1;
        }

        // ---- store P (tf32) to warp-private smem ----
        #pragma unroll
        for (int nt = 0; nt < 8; nt++) {
            uint2 p0 = { f2tf32(s[nt][0]), f2tf32(s[nt][1]) };
            uint2 p1 = { f2tf32(s[nt][2]), f2tf32(s[nt][3]) };
            *(uint2*)(Psw + g * PS_STRIDE + nt * 8 + 2 * tig) = p0;
            *(uint2*)(Psw + (g + 8) * PS_STRIDE + nt * 8 + 2 * tig) = p1;
        }
        __syncwarp();

        // ---- O += P V ----
        #pragma unroll
        for (int kt = 0; kt < 8; kt++) {
            uint32_t pa[4];
            pa[0] = Psw[g * PS_STRIDE + kt * 8 + tig];
            pa[1] = Psw[(g + 8) * PS_STRIDE + kt * 8 + tig];
            pa[2] = Psw[g * PS_STRIDE + kt * 8 + tig + 4];
            pa[3] = Psw[(g + 8) * PS_STRIDE + kt * 8 + tig + 4];
            #pragma unroll
            for (int nt = 0; nt < 8; nt++) {
                uint32_t b0 = Vs[(kt * 8 + tig) * VS_STRIDE + nt * 8 + g];
                uint32_t b1 = Vs[(kt * 8 + tig + 4) * VS_STRIDE + nt * 8 + g];
                mma_tf32(oacc[nt], pa, b0, b1);
            }
        }
        __syncwarp();   // protect Psw before next tile's stores
    }

    // ---- normalize + store [B,S,256] head-concat ----
    float inv0 = 1.0f / rl0, inv1 = 1.0f / rl1;
    float* Ob = O + ((size_t)b * SL + rw) * D_ + h * HD;
    #pragma unroll
    for (int nt = 0; nt < 8; nt++) {
        int col = nt * 8 + 2 * tig;
        float2 o0 = { oacc[nt][0] * inv0, oacc[nt][1] * inv0 };
        float2 o1 = { oacc[nt][2] * inv1, oacc[nt][3] * inv1 };
        *(float2*)(Ob + (size_t)g * D_ + col) = o0;
        *(float2*)(Ob + (size_t)(g + 8) * D_ + col) = o1;
    }
}

// ---------------------------------------------------------------------------
extern "C" void kernel_launch(void* const* d_in, const int* in_sizes, int n_in,
                              void* d_out, int out_size)
{
    const float* x_logic  = (const float*)d_in[0];
    const float* x_memory = (const float*)d_in[1];
    const int*   mask     = (const int*)  d_in[2];
    const float* Wq = (const float*)d_in[3];
    const float* bq = (const float*)d_in[4];
    const float* Wk = (const float*)d_in[5];
    const float* bk = (const float*)d_in[6];
    const float* Wv = (const float*)d_in[7];
    const float* bv = (const float*)d_in[8];
    const float* Wo = (const float*)d_in[9];
    const float* bo = (const float*)d_in[10];
    float* out = (float*)d_out;

    float *gQ, *gK, *gV, *gA; unsigned* gM;
    cudaGetSymbolAddress((void**)&gQ, g_Q);
    cudaGetSymbolAddress((void**)&gK, g_K);
    cudaGetSymbolAddress((void**)&gV, g_V);
    cudaGetSymbolAddress((void**)&gA, g_AT);
    cudaGetSymbolAddress((void**)&gM, g_M);

    mask_pack_kernel<<<SL * SL / 32 / 256, 256>>>(mask, gM);

    cudaFuncSetAttribute(gemm_qkv_kernel,
                         cudaFuncAttributeMaxDynamicSharedMemorySize, GEMM_SMEM_BYTES);
    cudaFuncSetAttribute(gemm_out_kernel,
                         cudaFuncAttributeMaxDynamicSharedMemorySize, GEMM_SMEM_BYTES);

    dim3 gqkv(B_ * SL / 128, D_ / 64, 3);   // 64 x 4 x 3 = 768 blocks
    gemm_qkv_kernel<<<gqkv, 256, GEMM_SMEM_BYTES>>>(
        x_logic, x_memory, Wq, bq, Wk, bk, Wv, bv, gQ, gK, gV);

    const int smem_bytes = SMEM_WORDS * (int)sizeof(uint32_t);
    cudaFuncSetAttribute(flash_tc_kernel,
                         cudaFuncAttributeMaxDynamicSharedMemorySize, smem_bytes);
    dim3 ga(SL / 128, H_, B_);              // 32 x 4 x 2 = 256 blocks
    flash_tc_kernel<<<ga, 256, smem_bytes>>>(gQ, gK, gV, gM, gA);

    dim3 gO(B_ * SL / 128, D_ / 64);        // 64 x 4
    gemm_out_kernel<<<gO, 256, GEMM_SMEM_BYTES>>>(gA, Wo, bo, out);
}

// round 9
// speedup vs baseline: 4.2789x; 1.0470x over previous
#include <cuda_runtime.h>
#include <cstdint>

// Problem constants
#define B_  2
#define H_  4
#define SL  4096
#define D_  256
#define HD  64

// Scratch (allocation-free rule: __device__ globals)
__device__ float    g_Q[B_ * H_ * SL * HD];   // [B,H,S,64], pre-scaled, tf32-rounded
__device__ float    g_K[B_ * H_ * SL * HD];   // tf32-rounded
__device__ float    g_V[B_ * H_ * SL * HD];   // tf32-rounded
__device__ float    g_AT[B_ * SL * D_];       // attention output [B,S,256]
__device__ unsigned g_M[SL * SL / 32];        // packed mask bits

// ---------------------------------------------------------------------------
// helpers
// ---------------------------------------------------------------------------
__device__ __forceinline__ uint32_t f2tf32(float x) {
    uint32_t u;
    asm("cvt.rna.tf32.f32 %0, %1;" : "=r"(u) : "f"(x));
    return u;
}

__device__ __forceinline__ void mma_tf32(float d[4], const uint32_t a[4],
                                         uint32_t b0, uint32_t b1) {
    asm volatile(
        "mma.sync.aligned.m16n8k8.row.col.f32.tf32.tf32.f32 "
        "{%0,%1,%2,%3}, {%4,%5,%6,%7}, {%8,%9}, {%0,%1,%2,%3};"
        : "+f"(d[0]), "+f"(d[1]), "+f"(d[2]), "+f"(d[3])
        : "r"(a[0]), "r"(a[1]), "r"(a[2]), "r"(a[3]), "r"(b0), "r"(b1));
}

__device__ __forceinline__ void cp16(uint32_t saddr, const void* g) {
    asm volatile("cp.async.ca.shared.global [%0], [%1], 16;"
                 :: "r"(saddr), "l"(g));
}
__device__ __forceinline__ void cp_commit() {
    asm volatile("cp.async.commit_group;");
}
template <int N>
__device__ __forceinline__ void cp_wait() {
    asm volatile("cp.async.wait_group %0;" :: "n"(N));
}

// ---------------------------------------------------------------------------
// Pack int32 mask [S,S] into bitmask (1 bit/element).
// ---------------------------------------------------------------------------
__global__ __launch_bounds__(256) void mask_pack_kernel(
    const int* __restrict__ mask, unsigned* __restrict__ out)
{
    int idx = blockIdx.x * 256 + threadIdx.x;
    const int* p = mask + (size_t)idx * 32;
    unsigned w = 0;
    #pragma unroll
    for (int i = 0; i < 32; i += 4) {
        int4 v = *(const int4*)(p + i);
        if (v.x) w |= 1u << i;
        if (v.y) w |= 1u << (i + 1);
        if (v.z) w |= 1u << (i + 2);
        if (v.w) w |= 1u << (i + 3);
    }
    out[idx] = w;
}

// ---------------------------------------------------------------------------
// Shared GEMM core: 128x64 tile, BK=64, tf32 mma, A-prefetch pipeline.
// ---------------------------------------------------------------------------
#define GA_STRIDE 68
#define GW_STRIDE 68
#define GA_WORDS (128 * GA_STRIDE)
#define GW_WORDS (64 * GW_STRIDE)
#define GEMM_SMEM_BYTES ((GA_WORDS + GW_WORDS) * 4)

struct GemmCtx {
    int t, lane, w, g, tig, rw;
};

__device__ __forceinline__ void gemm_core(
    uint32_t* As, uint32_t* Ws,
    const float* __restrict__ A, const float* __restrict__ W,
    int m0, int n0, const GemmCtx& cx, float acc[8][4])
{
    const int t = cx.t;

    float4 ra[8];
    #pragma unroll
    for (int i = 0; i < 8; i++) {
        int f  = t + i * 256;
        int r  = f >> 4;
        int c4 = (f & 15) << 2;
        ra[i] = *(const float4*)(A + (size_t)(m0 + r) * 256 + c4);
    }

    #pragma unroll
    for (int ks = 0; ks < 4; ks++) {
        const int k0 = ks * 64;
        __syncthreads();
        #pragma unroll
        for (int i = 0; i < 8; i++) {
            int f  = t + i * 256;
            int r  = f >> 4;
            int c4 = (f & 15) << 2;
            uint4 ua = { f2tf32(ra[i].x), f2tf32(ra[i].y),
                         f2tf32(ra[i].z), f2tf32(ra[i].w) };
            *(uint4*)(As + r * GA_STRIDE + c4) = ua;
        }
        #pragma unroll
        for (int i = 0; i < 4; i++) {
            int f  = t + i * 256;
            int r  = f >> 4;
            int c4 = (f & 15) << 2;
            float4 wv = *(const float4*)(W + (size_t)(n0 + r) * 256 + k0 + c4);
            uint4 uw = { f2tf32(wv.x), f2tf32(wv.y), f2tf32(wv.z), f2tf32(wv.w) };
            *(uint4*)(Ws + r * GW_STRIDE + c4) = uw;
        }
        __syncthreads();

        if (ks < 3) {
            #pragma unroll
            for (int i = 0; i < 8; i++) {
                int f  = t + i * 256;
                int r  = f >> 4;
                int c4 = (f & 15) << 2;
                ra[i] = *(const float4*)(A + (size_t)(m0 + r) * 256 + k0 + 64 + c4);
            }
        }

        uint32_t af[8][4];
        #pragma unroll
        for (int kt = 0; kt < 8; kt++) {
            af[kt][0] = As[(cx.rw + cx.g) * GA_STRIDE + kt * 8 + cx.tig];
            af[kt][1] = As[(cx.rw + cx.g + 8) * GA_STRIDE + kt * 8 + cx.tig];
            af[kt][2] = As[(cx.rw + cx.g) * GA_STRIDE + kt * 8 + cx.tig + 4];
            af[kt][3] = As[(cx.rw + cx.g + 8) * GA_STRIDE + kt * 8 + cx.tig + 4];
        }
        #pragma unroll
        for (int nt = 0; nt < 8; nt++) {
            #pragma unroll
            for (int kt = 0; kt < 8; kt++) {
                uint32_t b0 = Ws[(nt * 8 + cx.g) * GW_STRIDE + kt * 8 + cx.tig];
                uint32_t b1 = Ws[(nt * 8 + cx.g) * GW_STRIDE + kt * 8 + cx.tig + 4];
                mma_tf32(acc[nt], af[kt], b0, b1);
            }
        }
    }
}

// ---------------------------------------------------------------------------
// Fused Q/K/V projection: grid (64, 4, 3); z selects {Q,K,V}.
// ---------------------------------------------------------------------------
__global__ __launch_bounds__(256, 2) void gemm_qkv_kernel(
    const float* __restrict__ xl, const float* __restrict__ xm,
    const float* __restrict__ Wq, const float* __restrict__ bq,
    const float* __restrict__ Wk, const float* __restrict__ bk,
    const float* __restrict__ Wv, const float* __restrict__ bv,
    float* __restrict__ Cq, float* __restrict__ Ck, float* __restrict__ Cv)
{
    extern __shared__ uint32_t smg[];
    uint32_t* As = smg;
    uint32_t* Ws = smg + GA_WORDS;

    const int z = blockIdx.z;
    const float* A    = (z == 2) ? xm : xl;
    const float* W    = (z == 0) ? Wq : (z == 1) ? Wk : Wv;
    const float* bias = (z == 0) ? bq : (z == 1) ? bk : bv;
    float*       C    = (z == 0) ? Cq : (z == 1) ? Ck : Cv;
    const float outScale = (z == 0) ? 0.125f : 1.0f;

    GemmCtx cx;
    cx.t = threadIdx.x; cx.lane = cx.t & 31; cx.w = cx.t >> 5;
    cx.g = cx.lane >> 2; cx.tig = cx.lane & 3; cx.rw = cx.w * 16;

    const int m0 = blockIdx.x * 128, n0 = blockIdx.y * 64;

    float acc[8][4];
    #pragma unroll
    for (int nt = 0; nt < 8; nt++)
        #pragma unroll
        for (int e = 0; e < 4; e++) acc[nt][e] = 0.0f;

    gemm_core(As, Ws, A, W, m0, n0, cx, acc);

    const int r0 = m0 + cx.rw + cx.g;
    const int r1 = r0 + 8;
    #pragma unroll
    for (int nt = 0; nt < 8; nt++) {
        int col = nt * 8 + 2 * cx.tig;
        float bi0 = __ldg(bias + n0 + col);
        float bi1 = __ldg(bias + n0 + col + 1);
        uint2 o0 = { f2tf32((acc[nt][0] + bi0) * outScale),
                     f2tf32((acc[nt][1] + bi1) * outScale) };
        uint2 o1 = { f2tf32((acc[nt][2] + bi0) * outScale),
                     f2tf32((acc[nt][3] + bi1) * outScale) };
        int bb0 = r0 >> 12, s0 = r0 & (SL - 1);
        int bb1 = r1 >> 12, s1 = r1 & (SL - 1);
        *(uint2*)(C + ((size_t)(bb0 * H_ + blockIdx.y) * SL + s0) * HD + col) = o0;
        *(uint2*)(C + ((size_t)(bb1 * H_ + blockIdx.y) * SL + s1) * HD + col) = o1;
    }
}

// ---------------------------------------------------------------------------
// Output GEMM: C = AT @ Wo^T + bo, row-major [M,256], fp32 out.
// ---------------------------------------------------------------------------
__global__ __launch_bounds__(256, 2) void gemm_out_kernel(
    const float* __restrict__ A, const float* __restrict__ W,
    const float* __restrict__ bias, float* __restrict__ C)
{
    extern __shared__ uint32_t smg[];
    uint32_t* As = smg;
    uint32_t* Ws = smg + GA_WORDS;

    GemmCtx cx;
    cx.t = threadIdx.x; cx.lane = cx.t & 31; cx.w = cx.t >> 5;
    cx.g = cx.lane >> 2; cx.tig = cx.lane & 3; cx.rw = cx.w * 16;

    const int m0 = blockIdx.x * 128, n0 = blockIdx.y * 64;

    float acc[8][4];
    #pragma unroll
    for (int nt = 0; nt < 8; nt++)
        #pragma unroll
        for (int e = 0; e < 4; e++) acc[nt][e] = 0.0f;

    gemm_core(As, Ws, A, W, m0, n0, cx, acc);

    const int r0 = m0 + cx.rw + cx.g;
    const int r1 = r0 + 8;
    #pragma unroll
    for (int nt = 0; nt < 8; nt++) {
        int col = nt * 8 + 2 * cx.tig;
        float bi0 = __ldg(bias + n0 + col);
        float bi1 = __ldg(bias + n0 + col + 1);
        float2 o0 = { acc[nt][0] + bi0, acc[nt][1] + bi1 };
        float2 o1 = { acc[nt][2] + bi0, acc[nt][3] + bi1 };
        *(float2*)(C + (size_t)r0 * 256 + n0 + col) = o0;
        *(float2*)(C + (size_t)r1 * 256 + n0 + col) = o1;
    }
}

// ---------------------------------------------------------------------------
// Flash attention v2: 8 warps x 32 q-rows = 256 q-rows/block, grid = 128
// blocks (exactly one wave). Each warp computes two stacked m16 tiles so
// every K/V b-fragment LDS feeds 2 MMAs. Q lives in its own smem region.
// ---------------------------------------------------------------------------
#define KS_STRIDE 68
#define VS_STRIDE 72
#define QS_STRIDE 68
#define PS_STRIDE 68
#define KS_TILE (64 * KS_STRIDE)
#define VS_TILE (64 * VS_STRIDE)
#define KS_OFF 0
#define VS_OFF (2 * KS_TILE)
#define QS_OFF (VS_OFF + 2 * VS_TILE)
#define QS_WARP (32 * QS_STRIDE)
#define PS_OFF (QS_OFF + 8 * QS_WARP)
#define PS_WARP (32 * PS_STRIDE)
#define FSMEM_WORDS (PS_OFF + 8 * PS_WARP)     // 52736 words = 210944 B
#define NTILES (SL / 64)

__global__ __launch_bounds__(256) void flash_tc_kernel(
    const float* __restrict__ Q, const float* __restrict__ K,
    const float* __restrict__ V, const unsigned* __restrict__ Mb,
    float* __restrict__ O)
{
    extern __shared__ uint32_t sm[];

    const int t    = threadIdx.x;
    const int lane = t & 31;
    const int w    = t >> 5;
    const int g    = lane >> 2;
    const int tig  = lane & 3;
    uint32_t* Qsw = sm + QS_OFF + w * QS_WARP;
    uint32_t* Psw = sm + PS_OFF + w * PS_WARP;

    const int q0 = blockIdx.x * 256;
    const int h  = blockIdx.y;
    const int b  = blockIdx.z;
    const int rw = q0 + w * 32;

    const float* Qb = Q + ((size_t)(b * H_ + h) * SL + rw) * HD;
    const float* Kb = K + (size_t)(b * H_ + h) * SL * HD;
    const float* Vb = V + (size_t)(b * H_ + h) * SL * HD;

    const uint32_t smem_u32 = (uint32_t)__cvta_generic_to_shared(sm);

    int cr[4], cc[4];
    #pragma unroll
    for (int i = 0; i < 4; i++) {
        int f = t + i * 256;
        cr[i] = f >> 4;
        cc[i] = (f & 15) << 2;
    }

    // ---- prologue: issue K/V tile 0 ----
    #pragma unroll
    for (int i = 0; i < 4; i++) {
        cp16(smem_u32 + (KS_OFF + cr[i] * KS_STRIDE + cc[i]) * 4,
             Kb + (size_t)cr[i] * HD + cc[i]);
        cp16(smem_u32 + (VS_OFF + cr[i] * VS_STRIDE + cc[i]) * 4,
             Vb + (size_t)cr[i] * HD + cc[i]);
    }
    cp_commit();

    // ---- stage this warp's 32x64 Q tile (already tf32 bits) ----
    #pragma unroll
    for (int i = 0; i < 16; i++) {
        int f  = lane + i * 32;
        int r  = f >> 4;
        int c4 = (f & 15) << 2;
        *(uint4*)(Qsw + r * QS_STRIDE + c4) = *(const uint4*)(Qb + r * HD + c4);
    }

    float oacc[2][8][4];
    #pragma unroll
    for (int mt = 0; mt < 2; mt++)
        #pragma unroll
        for (int nt = 0; nt < 8; nt++)
            #pragma unroll
            for (int e = 0; e < 4; e++) oacc[mt][nt][e] = 0.0f;

    float rm[2][2], rl[2][2];
    #pragma unroll
    for (int mt = 0; mt < 2; mt++) {
        rm[mt][0] = -3.0e38f; rm[mt][1] = -3.0e38f;
        rl[mt][0] = 0.0f;     rl[mt][1] = 0.0f;
    }

    const unsigned* Mr[2][2];
    Mr[0][0] = Mb + (size_t)(rw + g) * 128;
    Mr[0][1] = Mb + (size_t)(rw + g + 8) * 128;
    Mr[1][0] = Mb + (size_t)(rw + 16 + g) * 128;
    Mr[1][1] = Mb + (size_t)(rw + 24 + g) * 128;

    for (int kbi = 0; kbi < NTILES; kbi++) {
        const int cur = kbi & 1;
        uint32_t* Ks = sm + KS_OFF + cur * KS_TILE;
        uint32_t* Vs = sm + VS_OFF + cur * VS_TILE;

        __syncthreads();   // everyone done with buffer !cur
        if (kbi + 1 < NTILES) {
            const int nxt = (kbi + 1) & 1;
            const size_t gofs = (size_t)(kbi + 1) * 64 * HD;
            #pragma unroll
            for (int i = 0; i < 4; i++) {
                cp16(smem_u32 + (KS_OFF + nxt * KS_TILE + cr[i] * KS_STRIDE + cc[i]) * 4,
                     Kb + gofs + (size_t)cr[i] * HD + cc[i]);
                cp16(smem_u32 + (VS_OFF + nxt * VS_TILE + cr[i] * VS_STRIDE + cc[i]) * 4,
                     Vb + gofs + (size_t)cr[i] * HD + cc[i]);
            }
            cp_commit();
            cp_wait<1>();
        } else {
            cp_wait<0>();
        }
        __syncthreads();   // tile kbi visible (also covers first-use of Qsw)

        uint2 mw[2][2];
        #pragma unroll
        for (int mt = 0; mt < 2; mt++) {
            mw[mt][0] = *(const uint2*)(Mr[mt][0] + kbi * 2);
            mw[mt][1] = *(const uint2*)(Mr[mt][1] + kbi * 2);
        }

        // ---- S = Q K^T (b-fragment shared across both m16 tiles) ----
        float s[2][8][4];
        #pragma unroll
        for (int mt = 0; mt < 2; mt++)
            #pragma unroll
            for (int nt = 0; nt < 8; nt++)
                #pragma unroll
                for (int e = 0; e < 4; e++) s[mt][nt][e] = 0.0f;

        #pragma unroll
        for (int kt = 0; kt < 8; kt++) {
            uint32_t af[2][4];
            #pragma unroll
            for (int mt = 0; mt < 2; mt++) {
                af[mt][0] = Qsw[(mt * 16 + g) * QS_STRIDE + kt * 8 + tig];
                af[mt][1] = Qsw[(mt * 16 + g + 8) * QS_STRIDE + kt * 8 + tig];
                af[mt][2] = Qsw[(mt * 16 + g) * QS_STRIDE + kt * 8 + tig + 4];
                af[mt][3] = Qsw[(mt * 16 + g + 8) * QS_STRIDE + kt * 8 + tig + 4];
            }
            #pragma unroll
            for (int nt = 0; nt < 8; nt++) {
                uint32_t b0 = Ks[(nt * 8 + g) * KS_STRIDE + kt * 8 + tig];
                uint32_t b1 = Ks[(nt * 8 + g) * KS_STRIDE + kt * 8 + tig + 4];
                mma_tf32(s[0][nt], af[0], b0, b1);
                mma_tf32(s[1][nt], af[1], b0, b1);
            }
        }

        // ---- masking + online softmax + P store, per m16 tile ----
        #pragma unroll
        for (int mt = 0; mt < 2; mt++) {
            #pragma unroll
            for (int nt = 0; nt < 8; nt++) {
                unsigned w0 = (nt < 4) ? mw[mt][0].x : mw[mt][0].y;
                unsigned w1 = (nt < 4) ? mw[mt][1].x : mw[mt][1].y;
                int sh = (nt & 3) * 8 + 2 * tig;
                if (!((w0 >> sh) & 1))       s[mt][nt][0] = -1e9f;
                if (!((w0 >> (sh + 1)) & 1)) s[mt][nt][1] = -1e9f;
                if (!((w1 >> sh) & 1))       s[mt][nt][2] = -1e9f;
                if (!((w1 >> (sh + 1)) & 1)) s[mt][nt][3] = -1e9f;
            }

            float m0 = -3.0e38f, m1 = -3.0e38f;
            #pragma unroll
            for (int nt = 0; nt < 8; nt++) {
                m0 = fmaxf(m0, fmaxf(s[mt][nt][0], s[mt][nt][1]));
                m1 = fmaxf(m1, fmaxf(s[mt][nt][2], s[mt][nt][3]));
            }
            m0 = fmaxf(m0, __shfl_xor_sync(0xffffffffu, m0, 1));
            m0 = fmaxf(m0, __shfl_xor_sync(0xffffffffu, m0, 2));
            m1 = fmaxf(m1, __shfl_xor_sync(0xffffffffu, m1, 1));
            m1 = fmaxf(m1, __shfl_xor_sync(0xffffffffu, m1, 2));

            float nm0 = fmaxf(rm[mt][0], m0), nm1 = fmaxf(rm[mt][1], m1);
            float corr0 = __expf(rm[mt][0] - nm0), corr1 = __expf(rm[mt][1] - nm1);

            float pl0 = 0.0f, pl1 = 0.0f;
            #pragma unroll
            for (int nt = 0; nt < 8; nt++) {
                s[mt][nt][0] = __expf(s[mt][nt][0] - nm0);
                s[mt][nt][1] = __expf(s[mt][nt][1] - nm0);
                s[mt][nt][2] = __expf(s[mt][nt][2] - nm1);
                s[mt][nt][3] = __expf(s[mt][nt][3] - nm1);
                pl0 += s[mt][nt][0] + s[mt][nt][1];
                pl1 += s[mt][nt][2] + s[mt][nt][3];
            }
            pl0 += __shfl_xor_sync(0xffffffffu, pl0, 1);
            pl0 += __shfl_xor_sync(0xffffffffu, pl0, 2);
            pl1 += __shfl_xor_sync(0xffffffffu, pl1, 1);
            pl1 += __shfl_xor_sync(0xffffffffu, pl1, 2);

            rl[mt][0] = rl[mt][0] * corr0 + pl0;  rm[mt][0] = nm0;
            rl[mt][1] = rl[mt][1] * corr1 + pl1;  rm[mt][1] = nm1;

            #pragma unroll
            for (int nt = 0; nt < 8; nt++) {
                oacc[mt][nt][0] *= corr0; oacc[mt][nt][1] *= corr0;
                oacc[mt][nt][2] *= corr1; oacc[mt][nt][3] *= corr1;
            }

            #pragma unroll
            for (int nt = 0; nt < 8; nt++) {
                uint2 p0 = { f2tf32(s[mt][nt][0]), f2tf32(s[mt][nt][1]) };
                uint2 p1 = { f2tf32(s[mt][nt][2]), f2tf32(s[mt][nt][3]) };
                *(uint2*)(Psw + (mt * 16 + g) * PS_STRIDE + nt * 8 + 2 * tig) = p0;
                *(uint2*)(Psw + (mt * 16 + g + 8) * PS_STRIDE + nt * 8 + 2 * tig) = p1;
            }
        }
        __syncwarp();

        // ---- O += P V (b-fragment shared across both m16 tiles) ----
        #pragma unroll
        for (int kt = 0; kt < 8; kt++) {
            uint32_t pa[2][4];
            #pragma unroll
            for (int mt = 0; mt < 2; mt++) {
                pa[mt][0] = Psw[(mt * 16 + g) * PS_STRIDE + kt * 8 + tig];
                pa[mt][1] = Psw[(mt * 16 + g + 8) * PS_STRIDE + kt * 8 + tig];
                pa[mt][2] = Psw[(mt * 16 + g) * PS_STRIDE + kt * 8 + tig + 4];
                pa[mt][3] = Psw[(mt * 16 + g + 8) * PS_STRIDE + kt * 8 + tig + 4];
            }
            #pragma unroll
            for (int nt = 0; nt < 8; nt++) {
                uint32_t b0 = Vs[(kt * 8 + tig) * VS_STRIDE + nt * 8 + g];
                uint32_t b1 = Vs[(kt * 8 + tig + 4) * VS_STRIDE + nt * 8 + g];
                mma_tf32(oacc[0][nt], pa[0], b0, b1);
                mma_tf32(oacc[1][nt], pa[1], b0, b1);
            }
        }
        __syncwarp();   // protect Psw before next tile's stores
    }

    // ---- normalize + store [B,S,256] head-concat ----
    float* Ob = O + ((size_t)b * SL + rw) * D_ + h * HD;
    #pragma unroll
    for (int mt = 0; mt < 2; mt++) {
        float inv0 = 1.0f / rl[mt][0], inv1 = 1.0f / rl[mt][1];
        #pragma unroll
        for (int nt = 0; nt < 8; nt++) {
            int col = nt * 8 + 2 * tig;
            float2 o0 = { oacc[mt][nt][0] * inv0, oacc[mt][nt][1] * inv0 };
            float2 o1 = { oacc[mt][nt][2] * inv1, oacc[mt][nt][3] * inv1 };
            *(float2*)(Ob + (size_t)(mt * 16 + g) * D_ + col) = o0;
            *(float2*)(Ob + (size_t)(mt * 16 + g + 8) * D_ + col) = o1;
        }
    }
}

// ---------------------------------------------------------------------------
extern "C" void kernel_launch(void* const* d_in, const int* in_sizes, int n_in,
                              void* d_out, int out_size)
{
    const float* x_logic  = (const float*)d_in[0];
    const float* x_memory = (const float*)d_in[1];
    const int*   mask     = (const int*)  d_in[2];
    const float* Wq = (const float*)d_in[3];
    const float* bq = (const float*)d_in[4];
    const float* Wk = (const float*)d_in[5];
    const float* bk = (const float*)d_in[6];
    const float* Wv = (const float*)d_in[7];
    const float* bv = (const float*)d_in[8];
    const float* Wo = (const float*)d_in[9];
    const float* bo = (const float*)d_in[10];
    float* out = (float*)d_out;

    float *gQ, *gK, *gV, *gA; unsigned* gM;
    cudaGetSymbolAddress((void**)&gQ, g_Q);
    cudaGetSymbolAddress((void**)&gK, g_K);
    cudaGetSymbolAddress((void**)&gV, g_V);
    cudaGetSymbolAddress((void**)&gA, g_AT);
    cudaGetSymbolAddress((void**)&gM, g_M);

    mask_pack_kernel<<<SL * SL / 32 / 256, 256>>>(mask, gM);

    cudaFuncSetAttribute(gemm_qkv_kernel,
                         cudaFuncAttributeMaxDynamicSharedMemorySize, GEMM_SMEM_BYTES);
    cudaFuncSetAttribute(gemm_out_kernel,
                         cudaFuncAttributeMaxDynamicSharedMemorySize, GEMM_SMEM_BYTES);

    dim3 gqkv(B_ * SL / 128, D_ / 64, 3);   // 64 x 4 x 3 = 768 blocks
    gemm_qkv_kernel<<<gqkv, 256, GEMM_SMEM_BYTES>>>(
        x_logic, x_memory, Wq, bq, Wk, bk, Wv, bv, gQ, gK, gV);

    const int fsmem_bytes = FSMEM_WORDS * (int)sizeof(uint32_t);   // 210944
    cudaFuncSetAttribute(flash_tc_kernel,
                         cudaFuncAttributeMaxDynamicSharedMemorySize, fsmem_bytes);
    dim3 ga(SL / 256, H_, B_);              // 16 x 4 x 2 = 128 blocks, one wave
    flash_tc_kernel<<<ga, 256, fsmem_bytes>>>(gQ, gK, gV, gM, gA);

    dim3 gO(B_ * SL / 128, D_ / 64);        // 64 x 4
    gemm_out_kernel<<<gO, 256, GEMM_SMEM_BYTES>>>(gA, Wo, bo, out);
}